// round 2
// baseline (speedup 1.0000x reference)
#include <cuda_runtime.h>

// ---------------------------------------------------------------------------
// Swin WindowAttention, fp32 baseline with fma.rn.f32x2 packed FFMA GEMMs.
// Pipeline:
//   1) g_qkv[M,768] = x[M,256] @ [wq|wk|wv]   (3 GEMM launches)
//   2) per-(window,head) attention: scores+bias+mask -> softmax -> AV
//      writes g_attn[M,256] in (n,l,h*32+d) layout
//   3) out[M,256] = g_attn @ wo
// M = 4096*49 = 200704
// ---------------------------------------------------------------------------

#define N_WIN 4096
#define L_TOK 49
#define CH    256
#define NHEAD 8
#define DK    32
#define M_ROWS (N_WIN * L_TOK)   // 200704

// scratch (allocation-free rule: __device__ globals)
__device__ float g_qkv[(size_t)M_ROWS * 768];
__device__ float g_attn[(size_t)M_ROWS * CH];

// ----------------------------- GEMM ----------------------------------------
// C[M, n] (ldC given) = A[M,256] @ W[256,256] tile, 128x128x16 blocking,
// 8x8 per-thread micro-tile held as 32 packed f32x2 accumulators.

#define BM 128
#define BN 128
#define BK 16
#define TM 8
#define TN 8

__device__ __forceinline__ void gemm_body(const float* __restrict__ A,
                                          const float* __restrict__ W,
                                          float* __restrict__ C, int ldC)
{
    __shared__ float As[BK][BM];   // transposed A tile
    __shared__ float Bs[BK][BN];

    const int tid      = threadIdx.x;
    const int rowBlock = blockIdx.x * BM;
    const int colBlock = blockIdx.y * BN;
    const int trow     = (tid >> 4) * TM;   // 0..120
    const int tcol     = (tid & 15) * TN;   // 0..120

    unsigned long long acc[TM][TN / 2];
#pragma unroll
    for (int m = 0; m < TM; m++)
#pragma unroll
        for (int j = 0; j < TN / 2; j++) acc[m][j] = 0ull;

    for (int k0 = 0; k0 < CH; k0 += BK) {
        // A tile: 128 rows x 16 cols, store transposed. 512 float4 / 256 thr.
#pragma unroll
        for (int i = 0; i < 2; i++) {
            int s  = tid * 2 + i;
            int ar = s >> 2;             // 0..127
            int ac = (s & 3) << 2;       // 0,4,8,12
            float4 av = *(const float4*)&A[(rowBlock + ar) * CH + k0 + ac];
            As[ac + 0][ar] = av.x;
            As[ac + 1][ar] = av.y;
            As[ac + 2][ar] = av.z;
            As[ac + 3][ar] = av.w;
        }
        // B tile: 16 rows x 128 cols. 512 float4 / 256 thr.
#pragma unroll
        for (int i = 0; i < 2; i++) {
            int s  = tid * 2 + i;
            int br = s >> 5;             // 0..15
            int bc = (s & 31) << 2;      // 0..124
            *(float4*)&Bs[br][bc] =
                *(const float4*)&W[(k0 + br) * CH + colBlock + bc];
        }
        __syncthreads();

#pragma unroll
        for (int kk = 0; kk < BK; kk++) {
            float4 a0 = *(const float4*)&As[kk][trow];
            float4 a1 = *(const float4*)&As[kk][trow + 4];
            float a[TM] = {a0.x, a0.y, a0.z, a0.w, a1.x, a1.y, a1.z, a1.w};
            unsigned long long ad[TM];
#pragma unroll
            for (int m = 0; m < TM; m++)
                asm("mov.b64 %0, {%1, %1};" : "=l"(ad[m]) : "f"(a[m]));
            unsigned long long b[TN / 2];
#pragma unroll
            for (int j = 0; j < TN / 2; j++)
                b[j] = *(const unsigned long long*)&Bs[kk][tcol + j * 2];
#pragma unroll
            for (int m = 0; m < TM; m++)
#pragma unroll
                for (int j = 0; j < TN / 2; j++)
                    asm("fma.rn.f32x2 %0, %1, %2, %0;"
                        : "+l"(acc[m][j]) : "l"(ad[m]), "l"(b[j]));
        }
        __syncthreads();
    }

#pragma unroll
    for (int m = 0; m < TM; m++) {
        float* crow = &C[(rowBlock + trow + m) * ldC + colBlock + tcol];
#pragma unroll
        for (int j = 0; j < TN / 2; j++) {
            float lo, hi;
            asm("mov.b64 {%0, %1}, %2;" : "=f"(lo), "=f"(hi) : "l"(acc[m][j]));
            float2 v2 = make_float2(lo, hi);
            *(float2*)&crow[j * 2] = v2;
        }
    }
}

__global__ __launch_bounds__(256, 2)
void k_gemm_qkv(const float* __restrict__ x, const float* __restrict__ w,
                int sect)
{
    gemm_body(x, w, g_qkv + sect, 768);
}

__global__ __launch_bounds__(256, 2)
void k_gemm_out(const float* __restrict__ w, float* __restrict__ out)
{
    gemm_body(g_attn, w, out, CH);
}

// --------------------------- Attention -------------------------------------
// One CTA per (window, head). 4 warps; each warp owns query rows i = warp+4t.
// Row stride DK+1 = 33 in smem kills the K[j][d] bank conflict (lanes vary j).

__global__ __launch_bounds__(128)
void attn_kernel(const float* __restrict__ mask,
                 const float* __restrict__ bias_table,
                 const int* __restrict__ rel_index)
{
    __shared__ float Qs[L_TOK][DK + 1];
    __shared__ float Ks[L_TOK][DK + 1];
    __shared__ float Vs[L_TOK][DK + 1];
    __shared__ float sb[L_TOK * L_TOK];   // bias+mask, 2401 floats
    __shared__ float arow[4][64];

    const int bid = blockIdx.x;
    const int h   = bid & 7;
    const int n   = bid >> 3;
    const int tid = threadIdx.x;

    const float* base = g_qkv + (size_t)n * L_TOK * 768 + h * DK;
    for (int idx = tid; idx < L_TOK * DK; idx += 128) {
        int r = idx >> 5;
        int d = idx & 31;
        const float* row = base + r * 768;
        Qs[r][d] = row[d];
        Ks[r][d] = row[256 + d];
        Vs[r][d] = row[512 + d];
    }
    const float* mrow = mask + (size_t)(n & 63) * (L_TOK * L_TOK);
    for (int idx = tid; idx < L_TOK * L_TOK; idx += 128) {
        sb[idx] = bias_table[rel_index[idx] * NHEAD + h] + mrow[idx];
    }
    __syncthreads();

    const int warp = tid >> 5;
    const int lane = tid & 31;

    for (int i = warp; i < L_TOK; i += 4) {
        const int  j1   = lane + 32;
        const bool has1 = (j1 < L_TOK);   // lane < 17
        const int  j1c  = has1 ? j1 : 0;
        float acc0 = 0.f, acc1 = 0.f;
#pragma unroll
        for (int d = 0; d < DK; d++) {
            float qd = Qs[i][d];
            acc0 += qd * Ks[lane][d];
            acc1 += qd * Ks[j1c][d];
        }
        acc0 += sb[i * L_TOK + lane];
        acc1 = has1 ? (acc1 + sb[i * L_TOK + j1]) : -3.0e38f;

        float mx = fmaxf(acc0, acc1);
#pragma unroll
        for (int o = 16; o; o >>= 1)
            mx = fmaxf(mx, __shfl_xor_sync(0xffffffffu, mx, o));

        float e0 = __expf(acc0 - mx);
        float e1 = has1 ? __expf(acc1 - mx) : 0.f;
        float ssum = e0 + e1;
#pragma unroll
        for (int o = 16; o; o >>= 1)
            ssum += __shfl_xor_sync(0xffffffffu, ssum, o);

        arow[warp][lane] = e0;
        if (has1) arow[warp][j1] = e1;
        __syncwarp();

        float od = 0.f;
#pragma unroll
        for (int j = 0; j < L_TOK; j++)
            od += arow[warp][j] * Vs[j][lane];
        od *= (1.f / ssum);

        g_attn[(size_t)(n * L_TOK + i) * CH + h * DK + lane] = od;
        __syncwarp();
    }
}

// ----------------------------- launch --------------------------------------

extern "C" void kernel_launch(void* const* d_in, const int* in_sizes, int n_in,
                              void* d_out, int out_size)
{
    (void)in_sizes; (void)n_in; (void)out_size;
    const float* x    = (const float*)d_in[0];
    const float* mask = (const float*)d_in[1];
    const float* wq   = (const float*)d_in[2];
    const float* wk   = (const float*)d_in[3];
    const float* wv   = (const float*)d_in[4];
    const float* wo   = (const float*)d_in[5];
    const float* bias = (const float*)d_in[6];
    const int*   rel  = (const int*)d_in[7];
    float* out = (float*)d_out;

    dim3 gg(M_ROWS / BM, CH / BN);   // (1568, 2)
    k_gemm_qkv<<<gg, 256>>>(x, wq, 0);
    k_gemm_qkv<<<gg, 256>>>(x, wk, 256);
    k_gemm_qkv<<<gg, 256>>>(x, wv, 512);
    attn_kernel<<<N_WIN * NHEAD, 128>>>(mask, bias, rel);
    k_gemm_out<<<gg, 256>>>(wo, out);
}

// round 4
// speedup vs baseline: 1.7056x; 1.7056x over previous
#include <cuda_runtime.h>
#include <cuda_fp16.h>
#include <cstdint>

// ---------------------------------------------------------------------------
// Swin WindowAttention on GB300 (base sm_103 target: no tcgen05; use mma.sync)
//   GEMMs: fp16 mma.sync m16n8k16 with hi/lo error compensation (3 passes)
//   Attention: per-(window,head) fp32 CTA kernel
// ---------------------------------------------------------------------------

#define N_WIN 4096
#define L_TOK 49
#define CH    256
#define NHEAD 8
#define DK    32
#define M_ROWS (N_WIN * L_TOK)   // 200704

__device__ float  g_qkv[(size_t)M_ROWS * 768];
__device__ __half g_xh[(size_t)M_ROWS * CH];
__device__ __half g_xl[(size_t)M_ROWS * CH];
__device__ __half g_ah[(size_t)M_ROWS * CH];
__device__ __half g_al[(size_t)M_ROWS * CH];
__device__ __half g_wh[4 * 65536];
__device__ __half g_wl[4 * 65536];

// ------------------------------ helpers ------------------------------------

__device__ __forceinline__ uint32_t smem_u32(const void* p) {
    uint32_t a;
    asm("{ .reg .u64 t; cvta.to.shared.u64 t, %1; cvt.u32.u64 %0, t; }"
        : "=r"(a) : "l"(p));
    return a;
}

__device__ __forceinline__ void cp16(uint32_t dst, const void* src) {
    asm volatile("cp.async.cg.shared.global [%0], [%1], 16;"
                 :: "r"(dst), "l"(src));
}
#define CP_COMMIT() asm volatile("cp.async.commit_group;" ::: "memory")
#define CP_WAIT1()  asm volatile("cp.async.wait_group 1;" ::: "memory")
#define CP_WAIT0()  asm volatile("cp.async.wait_group 0;" ::: "memory")

__device__ __forceinline__ void ldsm_x4(uint32_t addr, uint32_t* r) {
    asm volatile("ldmatrix.sync.aligned.m8n8.x4.shared.b16 {%0,%1,%2,%3}, [%4];"
                 : "=r"(r[0]), "=r"(r[1]), "=r"(r[2]), "=r"(r[3]) : "r"(addr));
}
__device__ __forceinline__ void ldsm_x4_t(uint32_t addr, uint32_t* r) {
    asm volatile("ldmatrix.sync.aligned.m8n8.x4.trans.shared.b16 {%0,%1,%2,%3}, [%4];"
                 : "=r"(r[0]), "=r"(r[1]), "=r"(r[2]), "=r"(r[3]) : "r"(addr));
}
__device__ __forceinline__ void mma16816(float* c, const uint32_t* a,
                                         const uint32_t* b) {
    asm volatile(
        "mma.sync.aligned.m16n8k16.row.col.f32.f16.f16.f32 "
        "{%0,%1,%2,%3}, {%4,%5,%6,%7}, {%8,%9}, {%0,%1,%2,%3};"
        : "+f"(c[0]), "+f"(c[1]), "+f"(c[2]), "+f"(c[3])
        : "r"(a[0]), "r"(a[1]), "r"(a[2]), "r"(a[3]), "r"(b[0]), "r"(b[1]));
}

// ------------------------------ split kernels --------------------------------

__device__ __forceinline__ void split1(float v, __half& h, __half& l) {
    h = __float2half_rn(v);
    l = __float2half_rn(v - __half2float(h));
}

__global__ void k_split_x(const float* __restrict__ x) {
    int i = blockIdx.x * blockDim.x + threadIdx.x;       // float4 index
    const int n4 = (M_ROWS * CH) / 4;
    if (i >= n4) return;
    float4 v = ((const float4*)x)[i];
    __half h0, l0, h1, l1, h2, l2, h3, l3;
    split1(v.x, h0, l0); split1(v.y, h1, l1);
    split1(v.z, h2, l2); split1(v.w, h3, l3);
    ((__half2*)g_xh)[i * 2]     = __halves2half2(h0, h1);
    ((__half2*)g_xh)[i * 2 + 1] = __halves2half2(h2, h3);
    ((__half2*)g_xl)[i * 2]     = __halves2half2(l0, l1);
    ((__half2*)g_xl)[i * 2 + 1] = __halves2half2(l2, l3);
}

__global__ void k_split_w(const float* __restrict__ w, int sect) {
    int i = blockIdx.x * blockDim.x + threadIdx.x;       // float4 index
    if (i >= 65536 / 4) return;
    float4 v = ((const float4*)w)[i];
    __half h0, l0, h1, l1, h2, l2, h3, l3;
    split1(v.x, h0, l0); split1(v.y, h1, l1);
    split1(v.z, h2, l2); split1(v.w, h3, l3);
    size_t base = (size_t)sect * 65536 / 2;              // half2 index base
    ((__half2*)g_wh)[base + i * 2]     = __halves2half2(h0, h1);
    ((__half2*)g_wh)[base + i * 2 + 1] = __halves2half2(h2, h3);
    ((__half2*)g_wl)[base + i * 2]     = __halves2half2(l0, l1);
    ((__half2*)g_wl)[base + i * 2 + 1] = __halves2half2(l2, l3);
}

// ------------------------------ GEMM ----------------------------------------
// C[M, 256] = A[M, 256] @ W[256, 256], hi/lo fp16 operands in smem.
// BM=128 BN=128 BK=32, 8 warps (4 m x 2 n), warp tile 32m x 64n.
// A smem [128][40] halfs (pad 40 -> conflict-free ldmatrix),
// B smem [32][136] halfs row-major [k][n] (trans at ldmatrix).

#define AROW 40
#define BROW 136
#define O_AH 0
#define O_AL 10240
#define O_BH 20480
#define O_BL 29184
#define S_BUF 37888
#define SMEM_BYTES (2 * S_BUF)

__global__ __launch_bounds__(256, 2)
void k_hgemm(int srcAttn, int wsect, float* __restrict__ Cext, int coff, int ldC)
{
    extern __shared__ char smem[];
    const uint32_t sb = smem_u32(smem);
    const int tid  = threadIdx.x;
    const int lane = tid & 31;
    const int wid  = tid >> 5;
    const int warp_m = wid & 3;       // 0..3 -> 32 rows each
    const int warp_n = wid >> 2;      // 0..1 -> 64 cols each
    const int rowBlock = blockIdx.x * 128;
    const int col0     = blockIdx.y * 128;

    const __half* Ah = srcAttn ? g_ah : g_xh;
    const __half* Al = srcAttn ? g_al : g_xl;
    const __half* Wh = g_wh + (size_t)wsect * 65536;
    const __half* Wl = g_wl + (size_t)wsect * 65536;
    float* C = Cext ? Cext : (g_qkv + coff);

    // per-thread copy coordinates
    const int ar  = tid >> 1;                 // A row 0..127
    const int ak0 = (tid & 1) * 16;           // A k-seg base (halfs)
    const int bk  = tid >> 3;                 // B k row 0..31
    const int bn0 = (tid & 7) * 16;           // B n base (halfs)

    float acc[2][8][4];
#pragma unroll
    for (int mt = 0; mt < 2; mt++)
#pragma unroll
        for (int nt = 0; nt < 8; nt++)
#pragma unroll
            for (int i = 0; i < 4; i++) acc[mt][nt][i] = 0.f;

    auto issue = [&](int c, int buf) {
        uint32_t s = sb + buf * S_BUF;
        const __half* ga = Ah + (size_t)(rowBlock + ar) * CH + c * 32 + ak0;
        const __half* gl = Al + (size_t)(rowBlock + ar) * CH + c * 32 + ak0;
        uint32_t da = s + O_AH + ar * (AROW * 2) + ak0 * 2;
        uint32_t dl = s + O_AL + ar * (AROW * 2) + ak0 * 2;
        cp16(da, ga); cp16(da + 16, ga + 8);
        cp16(dl, gl); cp16(dl + 16, gl + 8);
        const __half* gw = Wh + (size_t)(c * 32 + bk) * CH + col0 + bn0;
        const __half* gv = Wl + (size_t)(c * 32 + bk) * CH + col0 + bn0;
        uint32_t db = s + O_BH + bk * (BROW * 2) + bn0 * 2;
        uint32_t dv = s + O_BL + bk * (BROW * 2) + bn0 * 2;
        cp16(db, gw); cp16(db + 16, gw + 8);
        cp16(dv, gv); cp16(dv + 16, gv + 8);
        CP_COMMIT();
    };

    // ldmatrix lane address pieces
    const int arow_l = warp_m * 32 + (lane & 15);          // + mt*16
    const int acol_l = (lane >> 4) * 8;                    // + ks*16
    const int brow_l = (lane & 7) + ((lane >> 3) & 1) * 8; // + ks*16
    const int bcol_l = warp_n * 64 + (lane >> 4) * 8;      // + np*16

    issue(0, 0);

#pragma unroll 1
    for (int c = 0; c < 8; c++) {
        if (c < 7) { issue(c + 1, (c + 1) & 1); CP_WAIT1(); }
        else       { CP_WAIT0(); }
        __syncthreads();

        const uint32_t s = sb + (c & 1) * S_BUF;
#pragma unroll
        for (int ks = 0; ks < 2; ks++) {
            uint32_t ahr[2][4], alr[2][4], b[4][4];
            const uint32_t aoff = (acol_l + ks * 16) * 2;
#pragma unroll
            for (int mt = 0; mt < 2; mt++)
                ldsm_x4(s + O_AH + (arow_l + mt * 16) * (AROW * 2) + aoff,
                        ahr[mt]);
            const uint32_t brow = (brow_l + ks * 16) * (BROW * 2);
#pragma unroll
            for (int np = 0; np < 4; np++)
                ldsm_x4_t(s + O_BH + brow + (bcol_l + np * 16) * 2, b[np]);
#pragma unroll
            for (int mt = 0; mt < 2; mt++)
#pragma unroll
                for (int nt = 0; nt < 8; nt++)
                    mma16816(acc[mt][nt], ahr[mt], &b[nt >> 1][(nt & 1) * 2]);
            // lo(A) * hi(B)
#pragma unroll
            for (int mt = 0; mt < 2; mt++)
                ldsm_x4(s + O_AL + (arow_l + mt * 16) * (AROW * 2) + aoff,
                        alr[mt]);
#pragma unroll
            for (int mt = 0; mt < 2; mt++)
#pragma unroll
                for (int nt = 0; nt < 8; nt++)
                    mma16816(acc[mt][nt], alr[mt], &b[nt >> 1][(nt & 1) * 2]);
            // hi(A) * lo(B)
#pragma unroll
            for (int np = 0; np < 4; np++)
                ldsm_x4_t(s + O_BL + brow + (bcol_l + np * 16) * 2, b[np]);
#pragma unroll
            for (int mt = 0; mt < 2; mt++)
#pragma unroll
                for (int nt = 0; nt < 8; nt++)
                    mma16816(acc[mt][nt], ahr[mt], &b[nt >> 1][(nt & 1) * 2]);
        }
        __syncthreads();
    }

    // epilogue
    const int g = lane >> 2;
    const int tc = (lane & 3) * 2;
#pragma unroll
    for (int mt = 0; mt < 2; mt++) {
        const int r0 = rowBlock + warp_m * 32 + mt * 16 + g;
#pragma unroll
        for (int nt = 0; nt < 8; nt++) {
            const int cc = col0 + warp_n * 64 + nt * 8 + tc;
            *(float2*)&C[(size_t)r0 * ldC + cc] =
                make_float2(acc[mt][nt][0], acc[mt][nt][1]);
            *(float2*)&C[(size_t)(r0 + 8) * ldC + cc] =
                make_float2(acc[mt][nt][2], acc[mt][nt][3]);
        }
    }
}

// ------------------------------ attention ------------------------------------

__global__ __launch_bounds__(128)
void attn_kernel(const float* __restrict__ mask,
                 const float* __restrict__ bias_table,
                 const int* __restrict__ rel_index)
{
    __shared__ float Qs[L_TOK][DK + 1];
    __shared__ float Ks[L_TOK][DK + 1];
    __shared__ float Vs[L_TOK][DK + 1];
    __shared__ float sb[L_TOK * L_TOK];
    __shared__ float arow[4][64];

    const int bid = blockIdx.x;
    const int h   = bid & 7;
    const int n   = bid >> 3;
    const int tid = threadIdx.x;

    const float* base = g_qkv + (size_t)n * L_TOK * 768 + h * DK;
    for (int idx = tid; idx < L_TOK * DK; idx += 128) {
        int r = idx >> 5;
        int d = idx & 31;
        const float* row = base + r * 768;
        Qs[r][d] = row[d];
        Ks[r][d] = row[256 + d];
        Vs[r][d] = row[512 + d];
    }
    const float* mrow = mask + (size_t)(n & 63) * (L_TOK * L_TOK);
    for (int idx = tid; idx < L_TOK * L_TOK; idx += 128)
        sb[idx] = bias_table[rel_index[idx] * NHEAD + h] + mrow[idx];
    __syncthreads();

    const int warp = tid >> 5;
    const int lane = tid & 31;

    for (int i = warp; i < L_TOK; i += 4) {
        const int  j1   = lane + 32;
        const bool has1 = (j1 < L_TOK);
        const int  j1c  = has1 ? j1 : 0;
        float acc0 = 0.f, acc1 = 0.f;
#pragma unroll
        for (int d = 0; d < DK; d++) {
            float qd = Qs[i][d];
            acc0 += qd * Ks[lane][d];
            acc1 += qd * Ks[j1c][d];
        }
        acc0 += sb[i * L_TOK + lane];
        acc1 = has1 ? (acc1 + sb[i * L_TOK + j1]) : -3.0e38f;

        float mx = fmaxf(acc0, acc1);
#pragma unroll
        for (int o = 16; o; o >>= 1)
            mx = fmaxf(mx, __shfl_xor_sync(0xffffffffu, mx, o));

        float e0 = __expf(acc0 - mx);
        float e1 = has1 ? __expf(acc1 - mx) : 0.f;
        float ssum = e0 + e1;
#pragma unroll
        for (int o = 16; o; o >>= 1)
            ssum += __shfl_xor_sync(0xffffffffu, ssum, o);

        arow[warp][lane] = e0;
        if (has1) arow[warp][j1] = e1;
        __syncwarp();

        float od = 0.f;
#pragma unroll
        for (int j = 0; j < L_TOK; j++)
            od += arow[warp][j] * Vs[j][lane];
        od *= (1.f / ssum);

        size_t oi = (size_t)(n * L_TOK + i) * CH + h * DK + lane;
        __half hh = __float2half_rn(od);
        g_ah[oi] = hh;
        g_al[oi] = __float2half_rn(od - __half2float(hh));
        __syncwarp();
    }
}

// ------------------------------- launch --------------------------------------

extern "C" void kernel_launch(void* const* d_in, const int* in_sizes, int n_in,
                              void* d_out, int out_size)
{
    (void)in_sizes; (void)n_in; (void)out_size;
    const float* x    = (const float*)d_in[0];
    const float* mask = (const float*)d_in[1];
    const float* wq   = (const float*)d_in[2];
    const float* wk   = (const float*)d_in[3];
    const float* wv   = (const float*)d_in[4];
    const float* wo   = (const float*)d_in[5];
    const float* bias = (const float*)d_in[6];
    const int*   rel  = (const int*)d_in[7];
    float* out = (float*)d_out;

    cudaFuncSetAttribute(k_hgemm, cudaFuncAttributeMaxDynamicSharedMemorySize,
                         SMEM_BYTES);

    k_split_x<<<(M_ROWS * CH / 4 + 255) / 256, 256>>>(x);
    k_split_w<<<64, 256>>>(wq, 0);
    k_split_w<<<64, 256>>>(wk, 1);
    k_split_w<<<64, 256>>>(wv, 2);
    k_split_w<<<64, 256>>>(wo, 3);

    dim3 gg(M_ROWS / 128, 2);
    k_hgemm<<<gg, 256, SMEM_BYTES>>>(0, 0, nullptr, 0,   768);
    k_hgemm<<<gg, 256, SMEM_BYTES>>>(0, 1, nullptr, 256, 768);
    k_hgemm<<<gg, 256, SMEM_BYTES>>>(0, 2, nullptr, 512, 768);
    attn_kernel<<<N_WIN * NHEAD, 128>>>(mask, bias, rel);
    k_hgemm<<<gg, 256, SMEM_BYTES>>>(1, 3, out, 0, 256);
}

// round 5
// speedup vs baseline: 2.2561x; 1.3228x over previous
#include <cuda_runtime.h>
#include <cuda_fp16.h>
#include <cstdint>

// ---------------------------------------------------------------------------
// Swin WindowAttention, sm_103 base ISA (no tcgen05 — harness targets
// compute_103). GEMMs: fp16 mma.sync m16n8k16, 2-pass hi/lo compensation
// (activations split, weights single fp16). Attention: fp32 CTA kernel with
// precomputed bias+mask and float4 smem.
// ---------------------------------------------------------------------------

#define N_WIN 4096
#define L_TOK 49
#define CH    256
#define NHEAD 8
#define DK    32
#define M_ROWS (N_WIN * L_TOK)   // 200704
#define BM_STRIDE 2404           // bias+mask row stride (16B aligned)

__device__ float  g_qkv[(size_t)M_ROWS * 768];
__device__ __half g_xh[(size_t)M_ROWS * CH];
__device__ __half g_xl[(size_t)M_ROWS * CH];
__device__ __half g_ah[(size_t)M_ROWS * CH];
__device__ __half g_al[(size_t)M_ROWS * CH];
__device__ __half g_wqkv[256 * 768];       // [k][768] packed q|k|v
__device__ __half g_wo[256 * 256];
__device__ float  g_bm[512 * BM_STRIDE];   // (win&63, head) bias+mask

// ------------------------------ helpers ------------------------------------

__device__ __forceinline__ uint32_t smem_u32(const void* p) {
    uint32_t a;
    asm("{ .reg .u64 t; cvta.to.shared.u64 t, %1; cvt.u32.u64 %0, t; }"
        : "=r"(a) : "l"(p));
    return a;
}
__device__ __forceinline__ void cp16(uint32_t dst, const void* src) {
    asm volatile("cp.async.cg.shared.global [%0], [%1], 16;"
                 :: "r"(dst), "l"(src));
}
#define CP_COMMIT() asm volatile("cp.async.commit_group;" ::: "memory")
#define CP_WAIT1()  asm volatile("cp.async.wait_group 1;" ::: "memory")
#define CP_WAIT0()  asm volatile("cp.async.wait_group 0;" ::: "memory")

__device__ __forceinline__ void ldsm_x4(uint32_t addr, uint32_t* r) {
    asm volatile("ldmatrix.sync.aligned.m8n8.x4.shared.b16 {%0,%1,%2,%3}, [%4];"
                 : "=r"(r[0]), "=r"(r[1]), "=r"(r[2]), "=r"(r[3]) : "r"(addr));
}
__device__ __forceinline__ void ldsm_x4_t(uint32_t addr, uint32_t* r) {
    asm volatile("ldmatrix.sync.aligned.m8n8.x4.trans.shared.b16 {%0,%1,%2,%3}, [%4];"
                 : "=r"(r[0]), "=r"(r[1]), "=r"(r[2]), "=r"(r[3]) : "r"(addr));
}
__device__ __forceinline__ void mma16816(float* c, const uint32_t* a,
                                         const uint32_t* b) {
    asm volatile(
        "mma.sync.aligned.m16n8k16.row.col.f32.f16.f16.f32 "
        "{%0,%1,%2,%3}, {%4,%5,%6,%7}, {%8,%9}, {%0,%1,%2,%3};"
        : "+f"(c[0]), "+f"(c[1]), "+f"(c[2]), "+f"(c[3])
        : "r"(a[0]), "r"(a[1]), "r"(a[2]), "r"(a[3]), "r"(b[0]), "r"(b[1]));
}

__device__ __forceinline__ void split1(float v, __half& h, __half& l) {
    h = __float2half_rn(v);
    l = __float2half_rn(v - __half2float(h));
}

// ------------------------------ prep kernels --------------------------------

__global__ void k_split_x(const float* __restrict__ x) {
    int i = blockIdx.x * blockDim.x + threadIdx.x;
    if (i >= (M_ROWS * CH) / 4) return;
    float4 v = ((const float4*)x)[i];
    __half h0, l0, h1, l1, h2, l2, h3, l3;
    split1(v.x, h0, l0); split1(v.y, h1, l1);
    split1(v.z, h2, l2); split1(v.w, h3, l3);
    ((__half2*)g_xh)[i * 2]     = __halves2half2(h0, h1);
    ((__half2*)g_xh)[i * 2 + 1] = __halves2half2(h2, h3);
    ((__half2*)g_xl)[i * 2]     = __halves2half2(l0, l1);
    ((__half2*)g_xl)[i * 2 + 1] = __halves2half2(l2, l3);
}

__global__ void k_split_w(const float* __restrict__ wq,
                          const float* __restrict__ wk,
                          const float* __restrict__ wv,
                          const float* __restrict__ wo) {
    int gid = blockIdx.x * blockDim.x + threadIdx.x;   // float4 index, 65536
    if (gid >= 65536) return;
    int sect = gid >> 14;
    int i    = gid & 16383;                            // float4 within weight
    const float* src = (sect == 0) ? wq : (sect == 1) ? wk
                     : (sect == 2) ? wv : wo;
    float4 v = ((const float4*)src)[i];
    __half2 a = __halves2half2(__float2half_rn(v.x), __float2half_rn(v.y));
    __half2 b = __halves2half2(__float2half_rn(v.z), __float2half_rn(v.w));
    int k = (i * 4) >> 8;          // row 0..255
    int n = (i * 4) & 255;         // col
    if (sect < 3) {
        __half2* d = (__half2*)&g_wqkv[(size_t)k * 768 + sect * 256 + n];
        d[0] = a; d[1] = b;
    } else {
        __half2* d = (__half2*)&g_wo[(size_t)k * 256 + n];
        d[0] = a; d[1] = b;
    }
}

__global__ void k_bm(const float* __restrict__ mask,
                     const float* __restrict__ bias_table,
                     const int* __restrict__ rel_index) {
    const int bid = blockIdx.x;       // 0..511 = w*8 + h
    const int w   = bid >> 3;
    const int h   = bid & 7;
    float* dst = g_bm + (size_t)bid * BM_STRIDE;
    const float* mrow = mask + (size_t)w * (L_TOK * L_TOK);
    for (int i = threadIdx.x; i < L_TOK * L_TOK; i += blockDim.x)
        dst[i] = bias_table[rel_index[i] * NHEAD + h] + mrow[i];
}

// ------------------------------ GEMM ----------------------------------------
// BM=128 BN=128 BK=32, 8 warps (4m x 2n). A hi/lo fp16 + B fp16, 2 mma passes.

#define AROW 40
#define BROW 136
#define O_AH 0
#define O_AL 10240
#define O_B  20480
#define S_BUF 29184
#define SMEM_BYTES (2 * S_BUF)

__global__ __launch_bounds__(256, 2)
void k_hgemm(const __half* __restrict__ Ah, const __half* __restrict__ Al,
             const __half* __restrict__ Wh, int ldW,
             float* __restrict__ C, int ldC)
{
    extern __shared__ char smem[];
    const uint32_t sb = smem_u32(smem);
    const int tid  = threadIdx.x;
    const int lane = tid & 31;
    const int wid  = tid >> 5;
    const int warp_m = wid & 3;
    const int warp_n = wid >> 2;
    const int rowBlock = blockIdx.x * 128;
    const int col0     = blockIdx.y * 128;

    const int ar  = tid >> 1;
    const int ak0 = (tid & 1) * 16;
    const int bk  = tid >> 3;
    const int bn0 = (tid & 7) * 16;

    float acc[2][8][4];
#pragma unroll
    for (int mt = 0; mt < 2; mt++)
#pragma unroll
        for (int nt = 0; nt < 8; nt++)
#pragma unroll
            for (int i = 0; i < 4; i++) acc[mt][nt][i] = 0.f;

    auto issue = [&](int c, int buf) {
        uint32_t s = sb + buf * S_BUF;
        const __half* ga = Ah + (size_t)(rowBlock + ar) * CH + c * 32 + ak0;
        const __half* gl = Al + (size_t)(rowBlock + ar) * CH + c * 32 + ak0;
        uint32_t da = s + O_AH + ar * (AROW * 2) + ak0 * 2;
        uint32_t dl = s + O_AL + ar * (AROW * 2) + ak0 * 2;
        cp16(da, ga); cp16(da + 16, ga + 8);
        cp16(dl, gl); cp16(dl + 16, gl + 8);
        const __half* gw = Wh + (size_t)(c * 32 + bk) * ldW + col0 + bn0;
        uint32_t db = s + O_B + bk * (BROW * 2) + bn0 * 2;
        cp16(db, gw); cp16(db + 16, gw + 8);
        CP_COMMIT();
    };

    const int arow_l = warp_m * 32 + (lane & 15);
    const int acol_l = (lane >> 4) * 8;
    const int brow_l = (lane & 7) + ((lane >> 3) & 1) * 8;
    const int bcol_l = warp_n * 64 + (lane >> 4) * 8;

    issue(0, 0);

#pragma unroll 1
    for (int c = 0; c < 8; c++) {
        if (c < 7) { issue(c + 1, (c + 1) & 1); CP_WAIT1(); }
        else       { CP_WAIT0(); }
        __syncthreads();

        const uint32_t s = sb + (c & 1) * S_BUF;
#pragma unroll
        for (int ks = 0; ks < 2; ks++) {
            uint32_t ahr[2][4], alr[2][4], b[4][4];
            const uint32_t aoff = (acol_l + ks * 16) * 2;
#pragma unroll
            for (int mt = 0; mt < 2; mt++)
                ldsm_x4(s + O_AH + (arow_l + mt * 16) * (AROW * 2) + aoff,
                        ahr[mt]);
            const uint32_t brow = (brow_l + ks * 16) * (BROW * 2);
#pragma unroll
            for (int np = 0; np < 4; np++)
                ldsm_x4_t(s + O_B + brow + (bcol_l + np * 16) * 2, b[np]);
#pragma unroll
            for (int mt = 0; mt < 2; mt++)
#pragma unroll
                for (int nt = 0; nt < 8; nt++)
                    mma16816(acc[mt][nt], ahr[mt], &b[nt >> 1][(nt & 1) * 2]);
#pragma unroll
            for (int mt = 0; mt < 2; mt++)
                ldsm_x4(s + O_AL + (arow_l + mt * 16) * (AROW * 2) + aoff,
                        alr[mt]);
#pragma unroll
            for (int mt = 0; mt < 2; mt++)
#pragma unroll
                for (int nt = 0; nt < 8; nt++)
                    mma16816(acc[mt][nt], alr[mt], &b[nt >> 1][(nt & 1) * 2]);
        }
        __syncthreads();
    }

    const int g  = lane >> 2;
    const int tc = (lane & 3) * 2;
#pragma unroll
    for (int mt = 0; mt < 2; mt++) {
        const int r0 = rowBlock + warp_m * 32 + mt * 16 + g;
#pragma unroll
        for (int nt = 0; nt < 8; nt++) {
            const int cc = col0 + warp_n * 64 + nt * 8 + tc;
            *(float2*)&C[(size_t)r0 * ldC + cc] =
                make_float2(acc[mt][nt][0], acc[mt][nt][1]);
            *(float2*)&C[(size_t)(r0 + 8) * ldC + cc] =
                make_float2(acc[mt][nt][2], acc[mt][nt][3]);
        }
    }
}

// ------------------------------ attention -----------------------------------

#define QROW 36   // float stride (16B aligned, LDS.128 conflict-free)

__global__ __launch_bounds__(128)
void attn_kernel()
{
    __shared__ __align__(16) float Qs[L_TOK][QROW];
    __shared__ __align__(16) float Ks[L_TOK][QROW];
    __shared__ __align__(16) float Vs[L_TOK][QROW];
    __shared__ __align__(16) float sb[BM_STRIDE];
    __shared__ float arow[4][64];

    const int bid = blockIdx.x;
    const int h   = bid & 7;
    const int n   = bid >> 3;
    const int tid = threadIdx.x;

    const float* base = g_qkv + (size_t)n * L_TOK * 768 + h * DK;
    for (int idx = tid; idx < L_TOK * 8; idx += 128) {   // 392 float4 each
        int r = idx >> 3;
        int j = idx & 7;
        const float4* rp = (const float4*)(base + r * 768);
        ((float4*)Qs[r])[j] = rp[j];
        ((float4*)Ks[r])[j] = rp[64 + j];    // +256 floats
        ((float4*)Vs[r])[j] = rp[128 + j];   // +512 floats
    }
    const float4* bm4 = (const float4*)(g_bm + (size_t)(((n & 63) << 3) | h) * BM_STRIDE);
    for (int idx = tid; idx < BM_STRIDE / 4; idx += 128)
        ((float4*)sb)[idx] = bm4[idx];
    __syncthreads();

    const int warp = tid >> 5;
    const int lane = tid & 31;

    for (int i = warp; i < L_TOK; i += 4) {
        const int  j1   = lane + 32;
        const bool has1 = (j1 < L_TOK);
        const int  j1c  = has1 ? j1 : 0;
        float acc0 = 0.f, acc1 = 0.f;
#pragma unroll
        for (int j = 0; j < 8; j++) {
            float4 q = ((const float4*)Qs[i])[j];
            float4 k0 = ((const float4*)Ks[lane])[j];
            float4 k1 = ((const float4*)Ks[j1c])[j];
            acc0 += q.x * k0.x + q.y * k0.y + q.z * k0.z + q.w * k0.w;
            acc1 += q.x * k1.x + q.y * k1.y + q.z * k1.z + q.w * k1.w;
        }
        acc0 += sb[i * L_TOK + lane];
        acc1 = has1 ? (acc1 + sb[i * L_TOK + j1]) : -3.0e38f;

        float mx = fmaxf(acc0, acc1);
#pragma unroll
        for (int o = 16; o; o >>= 1)
            mx = fmaxf(mx, __shfl_xor_sync(0xffffffffu, mx, o));

        float e0 = __expf(acc0 - mx);
        float e1 = has1 ? __expf(acc1 - mx) : 0.f;
        float ssum = e0 + e1;
#pragma unroll
        for (int o = 16; o; o >>= 1)
            ssum += __shfl_xor_sync(0xffffffffu, ssum, o);

        arow[warp][lane] = e0;
        if (has1) arow[warp][j1] = e1;
        __syncwarp();

        float od = 0.f;
#pragma unroll
        for (int j = 0; j < L_TOK; j++)
            od += arow[warp][j] * Vs[j][lane];
        od *= (1.f / ssum);

        size_t oi = (size_t)(n * L_TOK + i) * CH + h * DK + lane;
        __half hh = __float2half_rn(od);
        g_ah[oi] = hh;
        g_al[oi] = __float2half_rn(od - __half2float(hh));
        __syncwarp();
    }
}

// ------------------------------- launch --------------------------------------

extern "C" void kernel_launch(void* const* d_in, const int* in_sizes, int n_in,
                              void* d_out, int out_size)
{
    (void)in_sizes; (void)n_in; (void)out_size;
    const float* x    = (const float*)d_in[0];
    const float* mask = (const float*)d_in[1];
    const float* wq   = (const float*)d_in[2];
    const float* wk   = (const float*)d_in[3];
    const float* wv   = (const float*)d_in[4];
    const float* wo   = (const float*)d_in[5];
    const float* bias = (const float*)d_in[6];
    const int*   rel  = (const int*)d_in[7];
    float* out = (float*)d_out;

    static __half *xh = nullptr, *xl = nullptr, *ah = nullptr, *al = nullptr;
    static __half *wqkv = nullptr, *woh = nullptr;
    static float  *qkv = nullptr;
    if (!xh) {
        cudaGetSymbolAddress((void**)&xh,   g_xh);
        cudaGetSymbolAddress((void**)&xl,   g_xl);
        cudaGetSymbolAddress((void**)&ah,   g_ah);
        cudaGetSymbolAddress((void**)&al,   g_al);
        cudaGetSymbolAddress((void**)&wqkv, g_wqkv);
        cudaGetSymbolAddress((void**)&woh,  g_wo);
        cudaGetSymbolAddress((void**)&qkv,  g_qkv);
        cudaFuncSetAttribute(k_hgemm,
                             cudaFuncAttributeMaxDynamicSharedMemorySize,
                             SMEM_BYTES);
    }

    k_split_x<<<(M_ROWS * CH / 4 + 255) / 256, 256>>>(x);
    k_split_w<<<256, 256>>>(wq, wk, wv, wo);
    k_bm<<<512, 256>>>(mask, bias, rel);
    k_hgemm<<<dim3(M_ROWS / 128, 6), 256, SMEM_BYTES>>>(xh, xl, wqkv, 768,
                                                        qkv, 768);
    attn_kernel<<<N_WIN * NHEAD, 128>>>();
    k_hgemm<<<dim3(M_ROWS / 128, 2), 256, SMEM_BYTES>>>(ah, al, woh, 256,
                                                        out, 256);
}

// round 6
// speedup vs baseline: 3.7784x; 1.6747x over previous
#include <cuda_runtime.h>
#include <cuda_fp16.h>
#include <cstdint>

// ---------------------------------------------------------------------------
// Swin WindowAttention, sm_103 base ISA (no tcgen05 in this harness).
//   GEMMs: single-pass fp16 mma.sync m16n8k16 (BM=128 BN=128 BK=64)
//   Attention: fp32, 4 query rows per warp-iteration (K/V smem reuse)
// ---------------------------------------------------------------------------

#define N_WIN 4096
#define L_TOK 49
#define CH    256
#define NHEAD 8
#define DK    32
#define M_ROWS (N_WIN * L_TOK)   // 200704
#define BM_STRIDE 2404

__device__ float  g_qkv[(size_t)M_ROWS * 768];
__device__ __half g_xh[(size_t)M_ROWS * CH];
__device__ __half g_ah[(size_t)M_ROWS * CH];
__device__ __half g_wqkv[256 * 768];
__device__ __half g_wo[256 * 256];
__device__ float  g_bm[512 * BM_STRIDE];

// ------------------------------ helpers ------------------------------------

__device__ __forceinline__ uint32_t smem_u32(const void* p) {
    uint32_t a;
    asm("{ .reg .u64 t; cvta.to.shared.u64 t, %1; cvt.u32.u64 %0, t; }"
        : "=r"(a) : "l"(p));
    return a;
}
__device__ __forceinline__ void cp16(uint32_t dst, const void* src) {
    asm volatile("cp.async.cg.shared.global [%0], [%1], 16;"
                 :: "r"(dst), "l"(src));
}
#define CP_COMMIT() asm volatile("cp.async.commit_group;" ::: "memory")
#define CP_WAIT1()  asm volatile("cp.async.wait_group 1;" ::: "memory")
#define CP_WAIT0()  asm volatile("cp.async.wait_group 0;" ::: "memory")

__device__ __forceinline__ void ldsm_x4(uint32_t addr, uint32_t* r) {
    asm volatile("ldmatrix.sync.aligned.m8n8.x4.shared.b16 {%0,%1,%2,%3}, [%4];"
                 : "=r"(r[0]), "=r"(r[1]), "=r"(r[2]), "=r"(r[3]) : "r"(addr));
}
__device__ __forceinline__ void ldsm_x4_t(uint32_t addr, uint32_t* r) {
    asm volatile("ldmatrix.sync.aligned.m8n8.x4.trans.shared.b16 {%0,%1,%2,%3}, [%4];"
                 : "=r"(r[0]), "=r"(r[1]), "=r"(r[2]), "=r"(r[3]) : "r"(addr));
}
__device__ __forceinline__ void mma16816(float* c, const uint32_t* a,
                                         const uint32_t* b) {
    asm volatile(
        "mma.sync.aligned.m16n8k16.row.col.f32.f16.f16.f32 "
        "{%0,%1,%2,%3}, {%4,%5,%6,%7}, {%8,%9}, {%0,%1,%2,%3};"
        : "+f"(c[0]), "+f"(c[1]), "+f"(c[2]), "+f"(c[3])
        : "r"(a[0]), "r"(a[1]), "r"(a[2]), "r"(a[3]), "r"(b[0]), "r"(b[1]));
}

// ------------------------------ prep kernels --------------------------------

__global__ void k_split_x(const float* __restrict__ x) {
    int i = blockIdx.x * blockDim.x + threadIdx.x;
    if (i >= (M_ROWS * CH) / 4) return;
    float4 v = ((const float4*)x)[i];
    ((__half2*)g_xh)[i * 2] =
        __halves2half2(__float2half_rn(v.x), __float2half_rn(v.y));
    ((__half2*)g_xh)[i * 2 + 1] =
        __halves2half2(__float2half_rn(v.z), __float2half_rn(v.w));
}

__global__ void k_split_w(const float* __restrict__ wq,
                          const float* __restrict__ wk,
                          const float* __restrict__ wv,
                          const float* __restrict__ wo) {
    int gid = blockIdx.x * blockDim.x + threadIdx.x;
    if (gid >= 65536) return;
    int sect = gid >> 14;
    int i    = gid & 16383;
    const float* src = (sect == 0) ? wq : (sect == 1) ? wk
                     : (sect == 2) ? wv : wo;
    float4 v = ((const float4*)src)[i];
    __half2 a = __halves2half2(__float2half_rn(v.x), __float2half_rn(v.y));
    __half2 b = __halves2half2(__float2half_rn(v.z), __float2half_rn(v.w));
    int k = (i * 4) >> 8;
    int n = (i * 4) & 255;
    if (sect < 3) {
        __half2* d = (__half2*)&g_wqkv[(size_t)k * 768 + sect * 256 + n];
        d[0] = a; d[1] = b;
    } else {
        __half2* d = (__half2*)&g_wo[(size_t)k * 256 + n];
        d[0] = a; d[1] = b;
    }
}

__global__ void k_bm(const float* __restrict__ mask,
                     const float* __restrict__ bias_table,
                     const int* __restrict__ rel_index) {
    const int bid = blockIdx.x;
    const int w   = bid >> 3;
    const int h   = bid & 7;
    float* dst = g_bm + (size_t)bid * BM_STRIDE;
    const float* mrow = mask + (size_t)w * (L_TOK * L_TOK);
    for (int i = threadIdx.x; i < L_TOK * L_TOK; i += blockDim.x)
        dst[i] = bias_table[rel_index[i] * NHEAD + h] + mrow[i];
}

// ------------------------------ GEMM ----------------------------------------
// BM=128 BN=128 BK=64, 8 warps (4m x 2n), single fp16 pass, double buffered.

#define AROWH 72     // A smem row stride (halfs)
#define BROWH 136    // B smem row stride (halfs)
#define O_A 0
#define O_B 18432
#define S_BUF 35840
#define SMEM_BYTES (2 * S_BUF)

__global__ __launch_bounds__(256, 2)
void k_hgemm(const __half* __restrict__ Ah, const __half* __restrict__ Wh,
             int ldW, float* __restrict__ C, int ldC)
{
    extern __shared__ char smem[];
    const uint32_t sb = smem_u32(smem);
    const int tid  = threadIdx.x;
    const int lane = tid & 31;
    const int wid  = tid >> 5;
    const int warp_m = wid & 3;
    const int warp_n = wid >> 2;
    const int rowBlock = blockIdx.y * 128;   // y = row block (L2 A reuse)
    const int col0     = blockIdx.x * 128;   // x = col block

    float acc[2][8][4];
#pragma unroll
    for (int mt = 0; mt < 2; mt++)
#pragma unroll
        for (int nt = 0; nt < 8; nt++)
#pragma unroll
            for (int i = 0; i < 4; i++) acc[mt][nt][i] = 0.f;

    auto issue = [&](int c, int buf) {
        uint32_t s = sb + buf * S_BUF;
#pragma unroll
        for (int q4 = 0; q4 < 4; q4++) {
            int q   = tid + 256 * q4;            // 0..1023
            int row = q >> 3;                    // A row 0..127
            int seg = (q & 7) * 8;               // halfs
            cp16(s + O_A + row * (AROWH * 2) + seg * 2,
                 Ah + (size_t)(rowBlock + row) * CH + c * 64 + seg);
        }
#pragma unroll
        for (int q4 = 0; q4 < 4; q4++) {
            int q   = tid + 256 * q4;
            int k   = q >> 4;                    // B k-row 0..63
            int seg = (q & 15) * 8;
            cp16(s + O_B + k * (BROWH * 2) + seg * 2,
                 Wh + (size_t)(c * 64 + k) * ldW + col0 + seg);
        }
        CP_COMMIT();
    };

    const int arow_l = warp_m * 32 + (lane & 15);
    const int acol_l = (lane >> 4) * 8;
    const int brow_l = (lane & 7) + ((lane >> 3) & 1) * 8;
    const int bcol_l = warp_n * 64 + (lane >> 4) * 8;

    issue(0, 0);

#pragma unroll 1
    for (int c = 0; c < 4; c++) {
        if (c < 3) { issue(c + 1, (c + 1) & 1); CP_WAIT1(); }
        else       { CP_WAIT0(); }
        __syncthreads();

        const uint32_t s = sb + (c & 1) * S_BUF;
#pragma unroll
        for (int ks = 0; ks < 4; ks++) {
            uint32_t a[2][4], b[4][4];
            const uint32_t aoff = (acol_l + ks * 16) * 2;
#pragma unroll
            for (int mt = 0; mt < 2; mt++)
                ldsm_x4(s + O_A + (arow_l + mt * 16) * (AROWH * 2) + aoff,
                        a[mt]);
            const uint32_t brow = (brow_l + ks * 16) * (BROWH * 2);
#pragma unroll
            for (int np = 0; np < 4; np++)
                ldsm_x4_t(s + O_B + brow + (bcol_l + np * 16) * 2, b[np]);
#pragma unroll
            for (int mt = 0; mt < 2; mt++)
#pragma unroll
                for (int nt = 0; nt < 8; nt++)
                    mma16816(acc[mt][nt], a[mt], &b[nt >> 1][(nt & 1) * 2]);
        }
        __syncthreads();
    }

    const int g  = lane >> 2;
    const int tc = (lane & 3) * 2;
#pragma unroll
    for (int mt = 0; mt < 2; mt++) {
        const int r0 = rowBlock + warp_m * 32 + mt * 16 + g;
#pragma unroll
        for (int nt = 0; nt < 8; nt++) {
            const int cc = col0 + warp_n * 64 + nt * 8 + tc;
            *(float2*)&C[(size_t)r0 * ldC + cc] =
                make_float2(acc[mt][nt][0], acc[mt][nt][1]);
            *(float2*)&C[(size_t)(r0 + 8) * ldC + cc] =
                make_float2(acc[mt][nt][2], acc[mt][nt][3]);
        }
    }
}

// ------------------------------ attention -----------------------------------
// 4 query rows per warp iteration: K/V smem loads amortized 4x.

#define QROW 36
#define ARS  56   // arow stride

__global__ __launch_bounds__(128)
void attn_kernel()
{
    __shared__ __align__(16) float Qs[L_TOK][QROW];
    __shared__ __align__(16) float Ks[L_TOK][QROW];
    __shared__ __align__(16) float Vs[L_TOK][QROW];
    __shared__ __align__(16) float sb[BM_STRIDE];
    __shared__ __align__(16) float arow[4][4][ARS];

    const int bid = blockIdx.x;
    const int h   = bid & 7;
    const int n   = bid >> 3;
    const int tid = threadIdx.x;

    const float* base = g_qkv + (size_t)n * L_TOK * 768 + h * DK;
    for (int idx = tid; idx < L_TOK * 8; idx += 128) {
        int r = idx >> 3;
        int j = idx & 7;
        const float4* rp = (const float4*)(base + r * 768);
        ((float4*)Qs[r])[j] = rp[j];
        ((float4*)Ks[r])[j] = rp[64 + j];
        ((float4*)Vs[r])[j] = rp[128 + j];
    }
    const float4* bm4 =
        (const float4*)(g_bm + (size_t)(((n & 63) << 3) | h) * BM_STRIDE);
    for (int idx = tid; idx < BM_STRIDE / 4; idx += 128)
        ((float4*)sb)[idx] = bm4[idx];
    __syncthreads();

    const int warp = tid >> 5;
    const int lane = tid & 31;
    const int j1   = lane + 32;
    const bool has1 = (j1 < L_TOK);
    const int  j1c  = has1 ? j1 : 0;

    for (int b0 = warp * 4; b0 < L_TOK; b0 += 16) {
        const int nr = (L_TOK - b0 < 4) ? (L_TOK - b0) : 4;

        float acc0[4] = {0.f, 0.f, 0.f, 0.f};
        float acc1[4] = {0.f, 0.f, 0.f, 0.f};
#pragma unroll
        for (int j = 0; j < 8; j++) {
            float4 k0 = ((const float4*)Ks[lane])[j];
            float4 k1 = ((const float4*)Ks[j1c])[j];
#pragma unroll
            for (int r = 0; r < 4; r++) {
                int ir = b0 + r;
                if (ir > L_TOK - 1) ir = L_TOK - 1;
                float4 q = ((const float4*)Qs[ir])[j];   // broadcast
                acc0[r] += q.x * k0.x + q.y * k0.y + q.z * k0.z + q.w * k0.w;
                acc1[r] += q.x * k1.x + q.y * k1.y + q.z * k1.z + q.w * k1.w;
            }
        }

        float rs[4];
#pragma unroll
        for (int r = 0; r < 4; r++) {
            if (r >= nr) { rs[r] = 1.f; continue; }
            const int i = b0 + r;
            float a0 = acc0[r] + sb[i * L_TOK + lane];
            float a1 = has1 ? (acc1[r] + sb[i * L_TOK + j1]) : -3.0e38f;
            float mx = fmaxf(a0, a1);
#pragma unroll
            for (int o = 16; o; o >>= 1)
                mx = fmaxf(mx, __shfl_xor_sync(0xffffffffu, mx, o));
            float e0 = __expf(a0 - mx);
            float e1 = has1 ? __expf(a1 - mx) : 0.f;
            float ss = e0 + e1;
#pragma unroll
            for (int o = 16; o; o >>= 1)
                ss += __shfl_xor_sync(0xffffffffu, ss, o);
            rs[r] = 1.f / ss;
            arow[warp][r][lane] = e0;
            if (has1) arow[warp][r][j1] = e1;
        }
        __syncwarp();

        float od[4] = {0.f, 0.f, 0.f, 0.f};
#pragma unroll
        for (int j = 0; j < L_TOK; j++) {
            float v = Vs[j][lane];
#pragma unroll
            for (int r = 0; r < 4; r++)
                od[r] += arow[warp][r][j] * v;       // arow: broadcast
        }
#pragma unroll
        for (int r = 0; r < 4; r++) {
            if (r < nr) {
                size_t oi = (size_t)(n * L_TOK + b0 + r) * CH + h * DK + lane;
                g_ah[oi] = __float2half_rn(od[r] * rs[r]);
            }
        }
        __syncwarp();
    }
}

// ------------------------------- launch --------------------------------------

extern "C" void kernel_launch(void* const* d_in, const int* in_sizes, int n_in,
                              void* d_out, int out_size)
{
    (void)in_sizes; (void)n_in; (void)out_size;
    const float* x    = (const float*)d_in[0];
    const float* mask = (const float*)d_in[1];
    const float* wq   = (const float*)d_in[2];
    const float* wk   = (const float*)d_in[3];
    const float* wv   = (const float*)d_in[4];
    const float* wo   = (const float*)d_in[5];
    const float* bias = (const float*)d_in[6];
    const int*   rel  = (const int*)d_in[7];
    float* out = (float*)d_out;

    static __half *xh = nullptr, *ah = nullptr, *wqkv = nullptr, *woh = nullptr;
    static float  *qkv = nullptr;
    if (!xh) {
        cudaGetSymbolAddress((void**)&xh,   g_xh);
        cudaGetSymbolAddress((void**)&ah,   g_ah);
        cudaGetSymbolAddress((void**)&wqkv, g_wqkv);
        cudaGetSymbolAddress((void**)&woh,  g_wo);
        cudaGetSymbolAddress((void**)&qkv,  g_qkv);
        cudaFuncSetAttribute(k_hgemm,
                             cudaFuncAttributeMaxDynamicSharedMemorySize,
                             SMEM_BYTES);
    }

    k_split_x<<<(M_ROWS * CH / 4 + 255) / 256, 256>>>(x);
    k_split_w<<<256, 256>>>(wq, wk, wv, wo);
    k_bm<<<512, 256>>>(mask, bias, rel);
    k_hgemm<<<dim3(6, M_ROWS / 128), 256, SMEM_BYTES>>>(xh, wqkv, 768,
                                                        qkv, 768);
    attn_kernel<<<N_WIN * NHEAD, 128>>>();
    k_hgemm<<<dim3(2, M_ROWS / 128), 256, SMEM_BYTES>>>(ah, woh, 256,
                                                        out, 256);
}

// round 7
// speedup vs baseline: 4.1736x; 1.1046x over previous
#include <cuda_runtime.h>
#include <cuda_fp16.h>
#include <cstdint>

// ---------------------------------------------------------------------------
// Swin WindowAttention, sm_103 base ISA.
//   QKV/out GEMMs: fp16 mma.sync m16n8k16 (BM=128 BN=128 BK=64); QKV GEMM
//   writes hi/lo fp16 planes (no fp32 intermediate).
//   Attention: HMMA per (window,head): QK 2-pass (K hi/lo), softmax in
//   fragments, AV 3-pass (P hi/lo regs, V hi/lo).
// ---------------------------------------------------------------------------

#define N_WIN 4096
#define L_TOK 49
#define CH    256
#define NHEAD 8
#define DK    32
#define M_ROWS (N_WIN * L_TOK)   // 200704
#define BM_STRIDE 2404

__device__ __half g_xh[(size_t)M_ROWS * CH];
__device__ __half g_qh[(size_t)M_ROWS * 768];   // hi plane of qkv
__device__ __half g_ql[(size_t)M_ROWS * 768];   // lo plane of qkv
__device__ __half g_ah[(size_t)M_ROWS * CH];    // attention output (fp16)
__device__ __half g_wqkv[256 * 768];
__device__ __half g_wo[256 * 256];
__device__ float  g_bm[512 * BM_STRIDE];

// ------------------------------ helpers ------------------------------------

__device__ __forceinline__ uint32_t smem_u32(const void* p) {
    uint32_t a;
    asm("{ .reg .u64 t; cvta.to.shared.u64 t, %1; cvt.u32.u64 %0, t; }"
        : "=r"(a) : "l"(p));
    return a;
}
__device__ __forceinline__ void cp16(uint32_t dst, const void* src) {
    asm volatile("cp.async.cg.shared.global [%0], [%1], 16;"
                 :: "r"(dst), "l"(src));
}
#define CP_COMMIT() asm volatile("cp.async.commit_group;" ::: "memory")
#define CP_WAIT1()  asm volatile("cp.async.wait_group 1;" ::: "memory")
#define CP_WAIT0()  asm volatile("cp.async.wait_group 0;" ::: "memory")

__device__ __forceinline__ void ldsm_x4(uint32_t addr, uint32_t* r) {
    asm volatile("ldmatrix.sync.aligned.m8n8.x4.shared.b16 {%0,%1,%2,%3}, [%4];"
                 : "=r"(r[0]), "=r"(r[1]), "=r"(r[2]), "=r"(r[3]) : "r"(addr));
}
__device__ __forceinline__ void ldsm_x4_t(uint32_t addr, uint32_t* r) {
    asm volatile("ldmatrix.sync.aligned.m8n8.x4.trans.shared.b16 {%0,%1,%2,%3}, [%4];"
                 : "=r"(r[0]), "=r"(r[1]), "=r"(r[2]), "=r"(r[3]) : "r"(addr));
}
__device__ __forceinline__ void mma16816(float* c, const uint32_t* a,
                                         const uint32_t* b) {
    asm volatile(
        "mma.sync.aligned.m16n8k16.row.col.f32.f16.f16.f32 "
        "{%0,%1,%2,%3}, {%4,%5,%6,%7}, {%8,%9}, {%0,%1,%2,%3};"
        : "+f"(c[0]), "+f"(c[1]), "+f"(c[2]), "+f"(c[3])
        : "r"(a[0]), "r"(a[1]), "r"(a[2]), "r"(a[3]), "r"(b[0]), "r"(b[1]));
}
__device__ __forceinline__ uint32_t pack_h2(float x, float y) {
    __half2 v = __halves2half2(__float2half_rn(x), __float2half_rn(y));
    return *(uint32_t*)&v;
}

// ------------------------------ prep kernels --------------------------------

__global__ void k_split_x(const float* __restrict__ x) {
    int i = blockIdx.x * blockDim.x + threadIdx.x;
    if (i >= (M_ROWS * CH) / 4) return;
    float4 v = ((const float4*)x)[i];
    ((__half2*)g_xh)[i * 2] =
        __halves2half2(__float2half_rn(v.x), __float2half_rn(v.y));
    ((__half2*)g_xh)[i * 2 + 1] =
        __halves2half2(__float2half_rn(v.z), __float2half_rn(v.w));
}

__global__ void k_split_w(const float* __restrict__ wq,
                          const float* __restrict__ wk,
                          const float* __restrict__ wv,
                          const float* __restrict__ wo) {
    int gid = blockIdx.x * blockDim.x + threadIdx.x;
    if (gid >= 65536) return;
    int sect = gid >> 14;
    int i    = gid & 16383;
    const float* src = (sect == 0) ? wq : (sect == 1) ? wk
                     : (sect == 2) ? wv : wo;
    float4 v = ((const float4*)src)[i];
    __half2 a = __halves2half2(__float2half_rn(v.x), __float2half_rn(v.y));
    __half2 b = __halves2half2(__float2half_rn(v.z), __float2half_rn(v.w));
    int k = (i * 4) >> 8;
    int n = (i * 4) & 255;
    if (sect < 3) {
        __half2* d = (__half2*)&g_wqkv[(size_t)k * 768 + sect * 256 + n];
        d[0] = a; d[1] = b;
    } else {
        __half2* d = (__half2*)&g_wo[(size_t)k * 256 + n];
        d[0] = a; d[1] = b;
    }
}

__global__ void k_bm(const float* __restrict__ mask,
                     const float* __restrict__ bias_table,
                     const int* __restrict__ rel_index) {
    const int bid = blockIdx.x;
    const int w   = bid >> 3;
    const int h   = bid & 7;
    float* dst = g_bm + (size_t)bid * BM_STRIDE;
    const float* mrow = mask + (size_t)w * (L_TOK * L_TOK);
    for (int i = threadIdx.x; i < L_TOK * L_TOK; i += blockDim.x)
        dst[i] = bias_table[rel_index[i] * NHEAD + h] + mrow[i];
}

// ------------------------------ GEMM ----------------------------------------
// BM=128 BN=128 BK=64. mode 0: write hi/lo fp16 planes (ldC=768);
// mode 1: write fp32 to Cf.

#define AROWH 72
#define BROWH 136
#define O_A 0
#define O_B 18432
#define S_BUF 35840
#define SMEM_BYTES (2 * S_BUF)

__global__ __launch_bounds__(256, 2)
void k_hgemm(const __half* __restrict__ Ah, const __half* __restrict__ Wh,
             int ldW, float* __restrict__ Cf, int ldC, int mode)
{
    extern __shared__ char smem[];
    const uint32_t sb = smem_u32(smem);
    const int tid  = threadIdx.x;
    const int lane = tid & 31;
    const int wid  = tid >> 5;
    const int warp_m = wid & 3;
    const int warp_n = wid >> 2;
    const int rowBlock = blockIdx.y * 128;
    const int col0     = blockIdx.x * 128;

    float acc[2][8][4];
#pragma unroll
    for (int mt = 0; mt < 2; mt++)
#pragma unroll
        for (int nt = 0; nt < 8; nt++)
#pragma unroll
            for (int i = 0; i < 4; i++) acc[mt][nt][i] = 0.f;

    auto issue = [&](int c, int buf) {
        uint32_t s = sb + buf * S_BUF;
#pragma unroll
        for (int q4 = 0; q4 < 4; q4++) {
            int q   = tid + 256 * q4;
            int row = q >> 3;
            int seg = (q & 7) * 8;
            cp16(s + O_A + row * (AROWH * 2) + seg * 2,
                 Ah + (size_t)(rowBlock + row) * CH + c * 64 + seg);
        }
#pragma unroll
        for (int q4 = 0; q4 < 4; q4++) {
            int q   = tid + 256 * q4;
            int k   = q >> 4;
            int seg = (q & 15) * 8;
            cp16(s + O_B + k * (BROWH * 2) + seg * 2,
                 Wh + (size_t)(c * 64 + k) * ldW + col0 + seg);
        }
        CP_COMMIT();
    };

    const int arow_l = warp_m * 32 + (lane & 15);
    const int acol_l = (lane >> 4) * 8;
    const int brow_l = (lane & 7) + ((lane >> 3) & 1) * 8;
    const int bcol_l = warp_n * 64 + (lane >> 4) * 8;

    issue(0, 0);

#pragma unroll 1
    for (int c = 0; c < 4; c++) {
        if (c < 3) { issue(c + 1, (c + 1) & 1); CP_WAIT1(); }
        else       { CP_WAIT0(); }
        __syncthreads();

        const uint32_t s = sb + (c & 1) * S_BUF;
#pragma unroll
        for (int ks = 0; ks < 4; ks++) {
            uint32_t a[2][4], b[4][4];
            const uint32_t aoff = (acol_l + ks * 16) * 2;
#pragma unroll
            for (int mt = 0; mt < 2; mt++)
                ldsm_x4(s + O_A + (arow_l + mt * 16) * (AROWH * 2) + aoff,
                        a[mt]);
            const uint32_t brow = (brow_l + ks * 16) * (BROWH * 2);
#pragma unroll
            for (int np = 0; np < 4; np++)
                ldsm_x4_t(s + O_B + brow + (bcol_l + np * 16) * 2, b[np]);
#pragma unroll
            for (int mt = 0; mt < 2; mt++)
#pragma unroll
                for (int nt = 0; nt < 8; nt++)
                    mma16816(acc[mt][nt], a[mt], &b[nt >> 1][(nt & 1) * 2]);
        }
        __syncthreads();
    }

    const int g  = lane >> 2;
    const int tc = (lane & 3) * 2;
    if (mode == 0) {
#pragma unroll
        for (int mt = 0; mt < 2; mt++) {
#pragma unroll
            for (int nt = 0; nt < 8; nt++) {
                const int cc = col0 + warp_n * 64 + nt * 8 + tc;
#pragma unroll
                for (int half_row = 0; half_row < 2; half_row++) {
                    const int r = rowBlock + warp_m * 32 + mt * 16 + g +
                                  half_row * 8;
                    float c0 = acc[mt][nt][half_row * 2];
                    float c1 = acc[mt][nt][half_row * 2 + 1];
                    __half h0 = __float2half_rn(c0);
                    __half h1 = __float2half_rn(c1);
                    size_t o = (size_t)r * 768 + cc;
                    *(__half2*)&g_qh[o] = __halves2half2(h0, h1);
                    *(__half2*)&g_ql[o] = __halves2half2(
                        __float2half_rn(c0 - __half2float(h0)),
                        __float2half_rn(c1 - __half2float(h1)));
                }
            }
        }
    } else {
#pragma unroll
        for (int mt = 0; mt < 2; mt++) {
            const int r0 = rowBlock + warp_m * 32 + mt * 16 + g;
#pragma unroll
            for (int nt = 0; nt < 8; nt++) {
                const int cc = col0 + warp_n * 64 + nt * 8 + tc;
                *(float2*)&Cf[(size_t)r0 * ldC + cc] =
                    make_float2(acc[mt][nt][0], acc[mt][nt][1]);
                *(float2*)&Cf[(size_t)(r0 + 8) * ldC + cc] =
                    make_float2(acc[mt][nt][2], acc[mt][nt][3]);
            }
        }
    }
}

// ------------------------------ attention (HMMA) ----------------------------
// One CTA per (window, head), 4 warps, warp w owns rows [16w, 16w+16).
// Scores: 64x64x32 (padded); QK 2-pass (K hi/lo). AV: 64x32x64, 3-pass.

#define KSTR 40   // smem row stride in halfs

__global__ __launch_bounds__(128)
void attn_kernel()
{
    __shared__ __align__(16) __half sQ [64 * KSTR];
    __shared__ __align__(16) __half sKh[64 * KSTR];
    __shared__ __align__(16) __half sKl[64 * KSTR];
    __shared__ __align__(16) __half sVh[64 * KSTR];
    __shared__ __align__(16) __half sVl[64 * KSTR];
    __shared__ __align__(16) float  ssb[BM_STRIDE];

    const int bid = blockIdx.x;
    const int h   = bid & 7;
    const int n   = bid >> 3;
    const int tid = threadIdx.x;

    // zero V padding rows 49..63 (cols 0..31): 15 rows x 4 int4 x 2 planes
    for (int idx = tid; idx < 120; idx += 128) {
        int p  = idx >= 60;
        int r  = 49 + ((idx % 60) >> 2);
        int q4 = idx & 3;
        *(int4*)((p ? sVl : sVh) + r * KSTR + q4 * 8) = make_int4(0, 0, 0, 0);
    }
    // load Q(hi), K(hi,lo), V(hi,lo): 5 planes x 49 rows x 4 int4
    {
        const size_t rb = (size_t)n * L_TOK * 768 + h * DK;
        for (int idx = tid; idx < 5 * 196; idx += 128) {
            int p   = idx / 196;
            int rem = idx - p * 196;
            int r   = rem >> 2;
            int q4  = rem & 3;
            const __half* src;
            __half* dst;
            switch (p) {
                case 0: src = g_qh + rb;       dst = sQ;  break;
                case 1: src = g_qh + rb + 256; dst = sKh; break;
                case 2: src = g_ql + rb + 256; dst = sKl; break;
                case 3: src = g_qh + rb + 512; dst = sVh; break;
                default: src = g_ql + rb + 512; dst = sVl; break;
            }
            *(int4*)(dst + r * KSTR + q4 * 8) =
                *(const int4*)(src + (size_t)r * 768 + q4 * 8);
        }
    }
    {
        const float* bm = g_bm + (size_t)(((n & 63) << 3) | h) * BM_STRIDE;
        for (int idx = tid; idx < BM_STRIDE / 4; idx += 128)
            ((int4*)ssb)[idx] = ((const int4*)bm)[idx];
    }
    __syncthreads();

    const int warp = tid >> 5;
    const int lane = tid & 31;
    const int g    = lane >> 2;
    const int t    = lane & 3;

    // ---- QK: scores c[8 ntiles][4] over 64 cols ----
    const uint32_t bq  = smem_u32(sQ);
    const uint32_t bkh = smem_u32(sKh);
    const uint32_t bkl = smem_u32(sKl);
    const int aRow = warp * 16 + (lane & 15);
    const int aCol = (lane >> 4) * 8;

    uint32_t qa[2][4];
    ldsm_x4(bq + (aRow * KSTR + aCol) * 2, qa[0]);
    ldsm_x4(bq + (aRow * KSTR + aCol + 16) * 2, qa[1]);

    float c[8][4];
#pragma unroll
    for (int nt = 0; nt < 8; nt++)
#pragma unroll
        for (int i = 0; i < 4; i++) c[nt][i] = 0.f;

#pragma unroll
    for (int pass = 0; pass < 2; pass++) {
        const uint32_t base = pass ? bkl : bkh;
#pragma unroll
        for (int kt = 0; kt < 2; kt++) {
#pragma unroll
            for (int jp = 0; jp < 4; jp++) {
                uint32_t kb[4];
                ldsm_x4(base + ((jp * 16 + (lane & 15)) * KSTR +
                                (lane >> 4) * 8 + kt * 16) * 2, kb);
                uint32_t b0[2] = {kb[0], kb[2]};
                uint32_t b1[2] = {kb[1], kb[3]};
                mma16816(c[jp * 2],     qa[kt], b0);
                mma16816(c[jp * 2 + 1], qa[kt], b1);
            }
        }
    }

    // ---- bias+mask, softmax (rows r0=warp*16+g, r1=r0+8) ----
    const int r0 = warp * 16 + g;
    const int r1 = r0 + 8;
    const int r0c = (r0 < L_TOK ? r0 : L_TOK - 1) * L_TOK;
    const int r1c = (r1 < L_TOK ? r1 : L_TOK - 1) * L_TOK;
#pragma unroll
    for (int nt = 0; nt < 8; nt++) {
        const int j0 = nt * 8 + t * 2;
        if (j0 < L_TOK) {
            c[nt][0] += ssb[r0c + j0];
            c[nt][2] += ssb[r1c + j0];
        } else { c[nt][0] = -3.0e38f; c[nt][2] = -3.0e38f; }
        if (j0 + 1 < L_TOK) {
            c[nt][1] += ssb[r0c + j0 + 1];
            c[nt][3] += ssb[r1c + j0 + 1];
        } else { c[nt][1] = -3.0e38f; c[nt][3] = -3.0e38f; }
    }

    float mx0 = -3.0e38f, mx1 = -3.0e38f;
#pragma unroll
    for (int nt = 0; nt < 8; nt++) {
        mx0 = fmaxf(mx0, fmaxf(c[nt][0], c[nt][1]));
        mx1 = fmaxf(mx1, fmaxf(c[nt][2], c[nt][3]));
    }
    mx0 = fmaxf(mx0, __shfl_xor_sync(0xffffffffu, mx0, 1));
    mx0 = fmaxf(mx0, __shfl_xor_sync(0xffffffffu, mx0, 2));
    mx1 = fmaxf(mx1, __shfl_xor_sync(0xffffffffu, mx1, 1));
    mx1 = fmaxf(mx1, __shfl_xor_sync(0xffffffffu, mx1, 2));

    float s0 = 0.f, s1 = 0.f;
#pragma unroll
    for (int nt = 0; nt < 8; nt++) {
        c[nt][0] = __expf(c[nt][0] - mx0); s0 += c[nt][0];
        c[nt][1] = __expf(c[nt][1] - mx0); s0 += c[nt][1];
        c[nt][2] = __expf(c[nt][2] - mx1); s1 += c[nt][2];
        c[nt][3] = __expf(c[nt][3] - mx1); s1 += c[nt][3];
    }
    s0 += __shfl_xor_sync(0xffffffffu, s0, 1);
    s0 += __shfl_xor_sync(0xffffffffu, s0, 2);
    s1 += __shfl_xor_sync(0xffffffffu, s1, 1);
    s1 += __shfl_xor_sync(0xffffffffu, s1, 2);
    const float rs0 = 1.f / s0;
    const float rs1 = 1.f / s1;

    // ---- AV: o[4 ntiles][4], 3 passes: Ph*Vh + Ph*Vl + Pl*Vh ----
    const uint32_t bvh = smem_u32(sVh);
    const uint32_t bvl = smem_u32(sVl);
    const int vRow = (lane & 7) + ((lane >> 3) & 1) * 8;
    const int vCol = (lane >> 4) * 8;

    float o[4][4];
#pragma unroll
    for (int nt = 0; nt < 4; nt++)
#pragma unroll
        for (int i = 0; i < 4; i++) o[nt][i] = 0.f;

#pragma unroll
    for (int kt = 0; kt < 4; kt++) {
        uint32_t ph[4], pl[4];
#pragma unroll
        for (int q = 0; q < 2; q++) {          // q=0 -> ntile 2kt, q=1 -> 2kt+1
            const float* cc = c[2 * kt + q];
            ph[q * 2]     = pack_h2(cc[0], cc[1]);
            ph[q * 2 + 1] = pack_h2(cc[2], cc[3]);
            __half2 hh0 = *(__half2*)&ph[q * 2];
            __half2 hh1 = *(__half2*)&ph[q * 2 + 1];
            pl[q * 2]     = pack_h2(cc[0] - __half2float(__low2half(hh0)),
                                    cc[1] - __half2float(__high2half(hh0)));
            pl[q * 2 + 1] = pack_h2(cc[2] - __half2float(__low2half(hh1)),
                                    cc[3] - __half2float(__high2half(hh1)));
        }
        uint32_t vh[2][4], vl[2][4];
        const uint32_t roff = (kt * 16 + vRow) * KSTR;
        ldsm_x4_t(bvh + (roff + vCol) * 2,      vh[0]);
        ldsm_x4_t(bvh + (roff + vCol + 16) * 2, vh[1]);
        ldsm_x4_t(bvl + (roff + vCol) * 2,      vl[0]);
        ldsm_x4_t(bvl + (roff + vCol + 16) * 2, vl[1]);
#pragma unroll
        for (int nt = 0; nt < 4; nt++) {
            uint32_t* vbh = &vh[nt >> 1][(nt & 1) * 2];
            uint32_t* vbl = &vl[nt >> 1][(nt & 1) * 2];
            mma16816(o[nt], ph, vbh);
            mma16816(o[nt], ph, vbl);
            mma16816(o[nt], pl, vbh);
        }
    }

    // ---- epilogue: out rows r0, r1 (if < 49), cols h*32 + nt*8 + 2t ----
    if (r0 < L_TOK) {
        __half* orow = g_ah + (size_t)(n * L_TOK + r0) * CH + h * DK;
#pragma unroll
        for (int nt = 0; nt < 4; nt++)
            *(__half2*)&orow[nt * 8 + t * 2] =
                __halves2half2(__float2half_rn(o[nt][0] * rs0),
                               __float2half_rn(o[nt][1] * rs0));
    }
    if (r1 < L_TOK) {
        __half* orow = g_ah + (size_t)(n * L_TOK + r1) * CH + h * DK;
#pragma unroll
        for (int nt = 0; nt < 4; nt++)
            *(__half2*)&orow[nt * 8 + t * 2] =
                __halves2half2(__float2half_rn(o[nt][2] * rs1),
                               __float2half_rn(o[nt][3] * rs1));
    }
}

// ------------------------------- launch --------------------------------------

extern "C" void kernel_launch(void* const* d_in, const int* in_sizes, int n_in,
                              void* d_out, int out_size)
{
    (void)in_sizes; (void)n_in; (void)out_size;
    const float* x    = (const float*)d_in[0];
    const float* mask = (const float*)d_in[1];
    const float* wq   = (const float*)d_in[2];
    const float* wk   = (const float*)d_in[3];
    const float* wv   = (const float*)d_in[4];
    const float* wo   = (const float*)d_in[5];
    const float* bias = (const float*)d_in[6];
    const int*   rel  = (const int*)d_in[7];
    float* out = (float*)d_out;

    static __half *xh = nullptr, *ah = nullptr, *wqkv = nullptr, *woh = nullptr;
    if (!xh) {
        cudaGetSymbolAddress((void**)&xh,   g_xh);
        cudaGetSymbolAddress((void**)&ah,   g_ah);
        cudaGetSymbolAddress((void**)&wqkv, g_wqkv);
        cudaGetSymbolAddress((void**)&woh,  g_wo);
        cudaFuncSetAttribute(k_hgemm,
                             cudaFuncAttributeMaxDynamicSharedMemorySize,
                             SMEM_BYTES);
    }

    k_split_x<<<(M_ROWS * CH / 4 + 255) / 256, 256>>>(x);
    k_split_w<<<256, 256>>>(wq, wk, wv, wo);
    k_bm<<<512, 256>>>(mask, bias, rel);
    k_hgemm<<<dim3(6, M_ROWS / 128), 256, SMEM_BYTES>>>(xh, wqkv, 768,
                                                        nullptr, 768, 0);
    attn_kernel<<<N_WIN * NHEAD, 128>>>();
    k_hgemm<<<dim3(2, M_ROWS / 128), 256, SMEM_BYTES>>>(ah, woh, 256,
                                                        out, 256, 1);
}

// round 8
// speedup vs baseline: 4.6061x; 1.1036x over previous
#include <cuda_runtime.h>
#include <cuda_fp16.h>
#include <cstdint>

// ---------------------------------------------------------------------------
// Swin WindowAttention, sm_103 base ISA.
//   QKV/out GEMMs: fp16 mma.sync m16n8k16 (BM=128 BN=128 BK=64); epilogue
//   staged through smem for STG.128 stores. QKV writes hi plane (+lo for K/V).
//   Attention: HMMA per (window,head): QK 2-pass (K hi/lo), softmax in
//   fragments, AV 3-pass (P hi/lo regs, V hi/lo).
// ---------------------------------------------------------------------------

#define N_WIN 4096
#define L_TOK 49
#define CH    256
#define NHEAD 8
#define DK    32
#define M_ROWS (N_WIN * L_TOK)   // 200704
#define BM_STRIDE 2404

__device__ __half g_xh[(size_t)M_ROWS * CH];
__device__ __half g_qh[(size_t)M_ROWS * 768];   // hi plane of qkv
__device__ __half g_ql[(size_t)M_ROWS * 768];   // lo plane (K/V sections only)
__device__ __half g_ah[(size_t)M_ROWS * CH];    // attention output (fp16)
__device__ __half g_wqkv[256 * 768];
__device__ __half g_wo[256 * 256];
__device__ float  g_bm[512 * BM_STRIDE];

// ------------------------------ helpers ------------------------------------

__device__ __forceinline__ uint32_t smem_u32(const void* p) {
    uint32_t a;
    asm("{ .reg .u64 t; cvta.to.shared.u64 t, %1; cvt.u32.u64 %0, t; }"
        : "=r"(a) : "l"(p));
    return a;
}
__device__ __forceinline__ void cp16(uint32_t dst, const void* src) {
    asm volatile("cp.async.cg.shared.global [%0], [%1], 16;"
                 :: "r"(dst), "l"(src));
}
#define CP_COMMIT() asm volatile("cp.async.commit_group;" ::: "memory")
#define CP_WAIT1()  asm volatile("cp.async.wait_group 1;" ::: "memory")
#define CP_WAIT0()  asm volatile("cp.async.wait_group 0;" ::: "memory")

__device__ __forceinline__ void ldsm_x4(uint32_t addr, uint32_t* r) {
    asm volatile("ldmatrix.sync.aligned.m8n8.x4.shared.b16 {%0,%1,%2,%3}, [%4];"
                 : "=r"(r[0]), "=r"(r[1]), "=r"(r[2]), "=r"(r[3]) : "r"(addr));
}
__device__ __forceinline__ void ldsm_x4_t(uint32_t addr, uint32_t* r) {
    asm volatile("ldmatrix.sync.aligned.m8n8.x4.trans.shared.b16 {%0,%1,%2,%3}, [%4];"
                 : "=r"(r[0]), "=r"(r[1]), "=r"(r[2]), "=r"(r[3]) : "r"(addr));
}
__device__ __forceinline__ void mma16816(float* c, const uint32_t* a,
                                         const uint32_t* b) {
    asm volatile(
        "mma.sync.aligned.m16n8k16.row.col.f32.f16.f16.f32 "
        "{%0,%1,%2,%3}, {%4,%5,%6,%7}, {%8,%9}, {%0,%1,%2,%3};"
        : "+f"(c[0]), "+f"(c[1]), "+f"(c[2]), "+f"(c[3])
        : "r"(a[0]), "r"(a[1]), "r"(a[2]), "r"(a[3]), "r"(b[0]), "r"(b[1]));
}
__device__ __forceinline__ uint32_t pack_h2(float x, float y) {
    __half2 v = __halves2half2(__float2half_rn(x), __float2half_rn(y));
    return *(uint32_t*)&v;
}

// ------------------------------ prep kernels --------------------------------

__global__ void k_split_x(const float* __restrict__ x) {
    int i = blockIdx.x * blockDim.x + threadIdx.x;
    if (i >= (M_ROWS * CH) / 4) return;
    float4 v = ((const float4*)x)[i];
    ((__half2*)g_xh)[i * 2] =
        __halves2half2(__float2half_rn(v.x), __float2half_rn(v.y));
    ((__half2*)g_xh)[i * 2 + 1] =
        __halves2half2(__float2half_rn(v.z), __float2half_rn(v.w));
}

__global__ void k_split_w(const float* __restrict__ wq,
                          const float* __restrict__ wk,
                          const float* __restrict__ wv,
                          const float* __restrict__ wo) {
    int gid = blockIdx.x * blockDim.x + threadIdx.x;
    if (gid >= 65536) return;
    int sect = gid >> 14;
    int i    = gid & 16383;
    const float* src = (sect == 0) ? wq : (sect == 1) ? wk
                     : (sect == 2) ? wv : wo;
    float4 v = ((const float4*)src)[i];
    __half2 a = __halves2half2(__float2half_rn(v.x), __float2half_rn(v.y));
    __half2 b = __halves2half2(__float2half_rn(v.z), __float2half_rn(v.w));
    int k = (i * 4) >> 8;
    int n = (i * 4) & 255;
    if (sect < 3) {
        __half2* d = (__half2*)&g_wqkv[(size_t)k * 768 + sect * 256 + n];
        d[0] = a; d[1] = b;
    } else {
        __half2* d = (__half2*)&g_wo[(size_t)k * 256 + n];
        d[0] = a; d[1] = b;
    }
}

__global__ void k_bm(const float* __restrict__ mask,
                     const float* __restrict__ bias_table,
                     const int* __restrict__ rel_index) {
    const int bid = blockIdx.x;
    const int w   = bid >> 3;
    const int h   = bid & 7;
    float* dst = g_bm + (size_t)bid * BM_STRIDE;
    const float* mrow = mask + (size_t)w * (L_TOK * L_TOK);
    for (int i = threadIdx.x; i < L_TOK * L_TOK; i += blockDim.x)
        dst[i] = bias_table[rel_index[i] * NHEAD + h] + mrow[i];
}

// ------------------------------ GEMM ----------------------------------------
// BM=128 BN=128 BK=64. mode 0: hi/lo fp16 planes (lo only for col0>=256);
// mode 1: fp32 to Cf. Epilogue staged through smem -> STG.128.

#define AROWH 72
#define BROWH 136
#define O_A 0
#define O_B 18432
#define S_BUF 35840
#define SMEM_BYTES (2 * S_BUF)
#define CS 136   // epilogue stage stride (floats); 128*136*4 = 69632 <= 71680

__global__ __launch_bounds__(256, 2)
void k_hgemm(const __half* __restrict__ Ah, const __half* __restrict__ Wh,
             int ldW, float* __restrict__ Cf, int ldC, int mode)
{
    extern __shared__ char smem[];
    const uint32_t sb = smem_u32(smem);
    const int tid  = threadIdx.x;
    const int lane = tid & 31;
    const int wid  = tid >> 5;
    const int warp_m = wid & 3;
    const int warp_n = wid >> 2;
    const int rowBlock = blockIdx.y * 128;
    const int col0     = blockIdx.x * 128;

    float acc[2][8][4];
#pragma unroll
    for (int mt = 0; mt < 2; mt++)
#pragma unroll
        for (int nt = 0; nt < 8; nt++)
#pragma unroll
            for (int i = 0; i < 4; i++) acc[mt][nt][i] = 0.f;

    auto issue = [&](int c, int buf) {
        uint32_t s = sb + buf * S_BUF;
#pragma unroll
        for (int q4 = 0; q4 < 4; q4++) {
            int q   = tid + 256 * q4;
            int row = q >> 3;
            int seg = (q & 7) * 8;
            cp16(s + O_A + row * (AROWH * 2) + seg * 2,
                 Ah + (size_t)(rowBlock + row) * CH + c * 64 + seg);
        }
#pragma unroll
        for (int q4 = 0; q4 < 4; q4++) {
            int q   = tid + 256 * q4;
            int k   = q >> 4;
            int seg = (q & 15) * 8;
            cp16(s + O_B + k * (BROWH * 2) + seg * 2,
                 Wh + (size_t)(c * 64 + k) * ldW + col0 + seg);
        }
        CP_COMMIT();
    };

    const int arow_l = warp_m * 32 + (lane & 15);
    const int acol_l = (lane >> 4) * 8;
    const int brow_l = (lane & 7) + ((lane >> 3) & 1) * 8;
    const int bcol_l = warp_n * 64 + (lane >> 4) * 8;

    issue(0, 0);

#pragma unroll 1
    for (int c = 0; c < 4; c++) {
        if (c < 3) { issue(c + 1, (c + 1) & 1); CP_WAIT1(); }
        else       { CP_WAIT0(); }
        __syncthreads();

        const uint32_t s = sb + (c & 1) * S_BUF;
#pragma unroll
        for (int ks = 0; ks < 4; ks++) {
            uint32_t a[2][4], b[4][4];
            const uint32_t aoff = (acol_l + ks * 16) * 2;
#pragma unroll
            for (int mt = 0; mt < 2; mt++)
                ldsm_x4(s + O_A + (arow_l + mt * 16) * (AROWH * 2) + aoff,
                        a[mt]);
            const uint32_t brow = (brow_l + ks * 16) * (BROWH * 2);
#pragma unroll
            for (int np = 0; np < 4; np++)
                ldsm_x4_t(s + O_B + brow + (bcol_l + np * 16) * 2, b[np]);
#pragma unroll
            for (int mt = 0; mt < 2; mt++)
#pragma unroll
                for (int nt = 0; nt < 8; nt++)
                    mma16816(acc[mt][nt], a[mt], &b[nt >> 1][(nt & 1) * 2]);
        }
        __syncthreads();
    }

    // ---- epilogue: stage fp32 tile in smem, re-read as contiguous chunks ----
    float* cs = (float*)smem;
    const int g  = lane >> 2;
    const int tc = (lane & 3) * 2;
#pragma unroll
    for (int mt = 0; mt < 2; mt++) {
        const int r = warp_m * 32 + mt * 16 + g;
#pragma unroll
        for (int nt = 0; nt < 8; nt++) {
            const int cc = warp_n * 64 + nt * 8 + tc;
            *(float2*)&cs[r * CS + cc] =
                make_float2(acc[mt][nt][0], acc[mt][nt][1]);
            *(float2*)&cs[(r + 8) * CS + cc] =
                make_float2(acc[mt][nt][2], acc[mt][nt][3]);
        }
    }
    __syncthreads();

    const bool wlo = (col0 >= 256);
#pragma unroll
    for (int i = 0; i < 8; i++) {
        const int id  = tid + 256 * i;
        const int row = id >> 4;
        const int col = (id & 15) * 8;
        float4 v0 = *(float4*)&cs[row * CS + col];
        float4 v1 = *(float4*)&cs[row * CS + col + 4];
        if (mode == 0) {
            uint4 hi, lo;
            hi.x = pack_h2(v0.x, v0.y); hi.y = pack_h2(v0.z, v0.w);
            hi.z = pack_h2(v1.x, v1.y); hi.w = pack_h2(v1.z, v1.w);
            __half2* hp = (__half2*)&hi;
            lo.x = pack_h2(v0.x - __low2float(hp[0]), v0.y - __high2float(hp[0]));
            lo.y = pack_h2(v0.z - __low2float(hp[1]), v0.w - __high2float(hp[1]));
            lo.z = pack_h2(v1.x - __low2float(hp[2]), v1.y - __high2float(hp[2]));
            lo.w = pack_h2(v1.z - __low2float(hp[3]), v1.w - __high2float(hp[3]));
            size_t o = (size_t)(rowBlock + row) * 768 + col0 + col;
            *(uint4*)&g_qh[o] = hi;
            if (wlo) *(uint4*)&g_ql[o] = lo;
        } else {
            size_t o = (size_t)(rowBlock + row) * ldC + col0 + col;
            *(float4*)&Cf[o]     = v0;
            *(float4*)&Cf[o + 4] = v1;
        }
    }
}

// ------------------------------ attention (HMMA) ----------------------------

#define KSTR 40

__global__ __launch_bounds__(128)
void attn_kernel()
{
    __shared__ __align__(16) __half sQ [64 * KSTR];
    __shared__ __align__(16) __half sKh[64 * KSTR];
    __shared__ __align__(16) __half sKl[64 * KSTR];
    __shared__ __align__(16) __half sVh[64 * KSTR];
    __shared__ __align__(16) __half sVl[64 * KSTR];
    __shared__ __align__(16) float  ssb[BM_STRIDE];

    const int bid = blockIdx.x;
    const int h   = bid & 7;
    const int n   = bid >> 3;
    const int tid = threadIdx.x;

    for (int idx = tid; idx < 120; idx += 128) {
        int p  = idx >= 60;
        int r  = 49 + ((idx % 60) >> 2);
        int q4 = idx & 3;
        *(int4*)((p ? sVl : sVh) + r * KSTR + q4 * 8) = make_int4(0, 0, 0, 0);
    }
    {
        const size_t rb = (size_t)n * L_TOK * 768 + h * DK;
        for (int idx = tid; idx < 5 * 196; idx += 128) {
            int p   = idx / 196;
            int rem = idx - p * 196;
            int r   = rem >> 2;
            int q4  = rem & 3;
            const __half* src;
            __half* dst;
            switch (p) {
                case 0: src = g_qh + rb;       dst = sQ;  break;
                case 1: src = g_qh + rb + 256; dst = sKh; break;
                case 2: src = g_ql + rb + 256; dst = sKl; break;
                case 3: src = g_qh + rb + 512; dst = sVh; break;
                default: src = g_ql + rb + 512; dst = sVl; break;
            }
            *(int4*)(dst + r * KSTR + q4 * 8) =
                *(const int4*)(src + (size_t)r * 768 + q4 * 8);
        }
    }
    {
        const float* bm = g_bm + (size_t)(((n & 63) << 3) | h) * BM_STRIDE;
        for (int idx = tid; idx < BM_STRIDE / 4; idx += 128)
            ((int4*)ssb)[idx] = ((const int4*)bm)[idx];
    }
    __syncthreads();

    const int warp = tid >> 5;
    const int lane = tid & 31;
    const int g    = lane >> 2;
    const int t    = lane & 3;

    const uint32_t bq  = smem_u32(sQ);
    const uint32_t bkh = smem_u32(sKh);
    const uint32_t bkl = smem_u32(sKl);
    const int aRow = warp * 16 + (lane & 15);
    const int aCol = (lane >> 4) * 8;

    uint32_t qa[2][4];
    ldsm_x4(bq + (aRow * KSTR + aCol) * 2, qa[0]);
    ldsm_x4(bq + (aRow * KSTR + aCol + 16) * 2, qa[1]);

    float c[8][4];
#pragma unroll
    for (int nt = 0; nt < 8; nt++)
#pragma unroll
        for (int i = 0; i < 4; i++) c[nt][i] = 0.f;

#pragma unroll
    for (int pass = 0; pass < 2; pass++) {
        const uint32_t base = pass ? bkl : bkh;
#pragma unroll
        for (int kt = 0; kt < 2; kt++) {
#pragma unroll
            for (int jp = 0; jp < 4; jp++) {
                uint32_t kb[4];
                ldsm_x4(base + ((jp * 16 + (lane & 15)) * KSTR +
                                (lane >> 4) * 8 + kt * 16) * 2, kb);
                uint32_t b0[2] = {kb[0], kb[2]};
                uint32_t b1[2] = {kb[1], kb[3]};
                mma16816(c[jp * 2],     qa[kt], b0);
                mma16816(c[jp * 2 + 1], qa[kt], b1);
            }
        }
    }

    const int r0 = warp * 16 + g;
    const int r1 = r0 + 8;
    const int r0c = (r0 < L_TOK ? r0 : L_TOK - 1) * L_TOK;
    const int r1c = (r1 < L_TOK ? r1 : L_TOK - 1) * L_TOK;
#pragma unroll
    for (int nt = 0; nt < 8; nt++) {
        const int j0 = nt * 8 + t * 2;
        if (j0 < L_TOK) {
            c[nt][0] += ssb[r0c + j0];
            c[nt][2] += ssb[r1c + j0];
        } else { c[nt][0] = -3.0e38f; c[nt][2] = -3.0e38f; }
        if (j0 + 1 < L_TOK) {
            c[nt][1] += ssb[r0c + j0 + 1];
            c[nt][3] += ssb[r1c + j0 + 1];
        } else { c[nt][1] = -3.0e38f; c[nt][3] = -3.0e38f; }
    }

    float mx0 = -3.0e38f, mx1 = -3.0e38f;
#pragma unroll
    for (int nt = 0; nt < 8; nt++) {
        mx0 = fmaxf(mx0, fmaxf(c[nt][0], c[nt][1]));
        mx1 = fmaxf(mx1, fmaxf(c[nt][2], c[nt][3]));
    }
    mx0 = fmaxf(mx0, __shfl_xor_sync(0xffffffffu, mx0, 1));
    mx0 = fmaxf(mx0, __shfl_xor_sync(0xffffffffu, mx0, 2));
    mx1 = fmaxf(mx1, __shfl_xor_sync(0xffffffffu, mx1, 1));
    mx1 = fmaxf(mx1, __shfl_xor_sync(0xffffffffu, mx1, 2));

    float s0 = 0.f, s1 = 0.f;
#pragma unroll
    for (int nt = 0; nt < 8; nt++) {
        c[nt][0] = __expf(c[nt][0] - mx0); s0 += c[nt][0];
        c[nt][1] = __expf(c[nt][1] - mx0); s0 += c[nt][1];
        c[nt][2] = __expf(c[nt][2] - mx1); s1 += c[nt][2];
        c[nt][3] = __expf(c[nt][3] - mx1); s1 += c[nt][3];
    }
    s0 += __shfl_xor_sync(0xffffffffu, s0, 1);
    s0 += __shfl_xor_sync(0xffffffffu, s0, 2);
    s1 += __shfl_xor_sync(0xffffffffu, s1, 1);
    s1 += __shfl_xor_sync(0xffffffffu, s1, 2);
    const float rs0 = 1.f / s0;
    const float rs1 = 1.f / s1;

    const uint32_t bvh = smem_u32(sVh);
    const uint32_t bvl = smem_u32(sVl);
    const int vRow = (lane & 7) + ((lane >> 3) & 1) * 8;
    const int vCol = (lane >> 4) * 8;

    float o[4][4];
#pragma unroll
    for (int nt = 0; nt < 4; nt++)
#pragma unroll
        for (int i = 0; i < 4; i++) o[nt][i] = 0.f;

#pragma unroll
    for (int kt = 0; kt < 4; kt++) {
        uint32_t ph[4], pl[4];
#pragma unroll
        for (int q = 0; q < 2; q++) {
            const float* cc = c[2 * kt + q];
            ph[q * 2]     = pack_h2(cc[0], cc[1]);
            ph[q * 2 + 1] = pack_h2(cc[2], cc[3]);
            __half2 hh0 = *(__half2*)&ph[q * 2];
            __half2 hh1 = *(__half2*)&ph[q * 2 + 1];
            pl[q * 2]     = pack_h2(cc[0] - __low2float(hh0),
                                    cc[1] - __high2float(hh0));
            pl[q * 2 + 1] = pack_h2(cc[2] - __low2float(hh1),
                                    cc[3] - __high2float(hh1));
        }
        uint32_t vh[2][4], vl[2][4];
        const uint32_t roff = (kt * 16 + vRow) * KSTR;
        ldsm_x4_t(bvh + (roff + vCol) * 2,      vh[0]);
        ldsm_x4_t(bvh + (roff + vCol + 16) * 2, vh[1]);
        ldsm_x4_t(bvl + (roff + vCol) * 2,      vl[0]);
        ldsm_x4_t(bvl + (roff + vCol + 16) * 2, vl[1]);
#pragma unroll
        for (int nt = 0; nt < 4; nt++) {
            uint32_t* vbh = &vh[nt >> 1][(nt & 1) * 2];
            uint32_t* vbl = &vl[nt >> 1][(nt & 1) * 2];
            mma16816(o[nt], ph, vbh);
            mma16816(o[nt], ph, vbl);
            mma16816(o[nt], pl, vbh);
        }
    }

    if (r0 < L_TOK) {
        __half* orow = g_ah + (size_t)(n * L_TOK + r0) * CH + h * DK;
#pragma unroll
        for (int nt = 0; nt < 4; nt++)
            *(__half2*)&orow[nt * 8 + t * 2] =
                __halves2half2(__float2half_rn(o[nt][0] * rs0),
                               __float2half_rn(o[nt][1] * rs0));
    }
    if (r1 < L_TOK) {
        __half* orow = g_ah + (size_t)(n * L_TOK + r1) * CH + h * DK;
#pragma unroll
        for (int nt = 0; nt < 4; nt++)
            *(__half2*)&orow[nt * 8 + t * 2] =
                __halves2half2(__float2half_rn(o[nt][2] * rs1),
                               __float2half_rn(o[nt][3] * rs1));
    }
}

// ------------------------------- launch --------------------------------------

extern "C" void kernel_launch(void* const* d_in, const int* in_sizes, int n_in,
                              void* d_out, int out_size)
{
    (void)in_sizes; (void)n_in; (void)out_size;
    const float* x    = (const float*)d_in[0];
    const float* mask = (const float*)d_in[1];
    const float* wq   = (const float*)d_in[2];
    const float* wk   = (const float*)d_in[3];
    const float* wv   = (const float*)d_in[4];
    const float* wo   = (const float*)d_in[5];
    const float* bias = (const float*)d_in[6];
    const int*   rel  = (const int*)d_in[7];
    float* out = (float*)d_out;

    static __half *xh = nullptr, *ah = nullptr, *wqkv = nullptr, *woh = nullptr;
    if (!xh) {
        cudaGetSymbolAddress((void**)&xh,   g_xh);
        cudaGetSymbolAddress((void**)&ah,   g_ah);
        cudaGetSymbolAddress((void**)&wqkv, g_wqkv);
        cudaGetSymbolAddress((void**)&woh,  g_wo);
        cudaFuncSetAttribute(k_hgemm,
                             cudaFuncAttributeMaxDynamicSharedMemorySize,
                             SMEM_BYTES);
    }

    k_split_x<<<(M_ROWS * CH / 4 + 255) / 256, 256>>>(x);
    k_split_w<<<256, 256>>>(wq, wk, wv, wo);
    k_bm<<<512, 256>>>(mask, bias, rel);
    k_hgemm<<<dim3(6, M_ROWS / 128), 256, SMEM_BYTES>>>(xh, wqkv, 768,
                                                        nullptr, 768, 0);
    attn_kernel<<<N_WIN * NHEAD, 128>>>();
    k_hgemm<<<dim3(2, M_ROWS / 128), 256, SMEM_BYTES>>>(ah, woh, 256,
                                                        out, 256, 1);
}

// round 9
// speedup vs baseline: 5.4528x; 1.1838x over previous
#include <cuda_runtime.h>
#include <cuda_fp16.h>
#include <cstdint>

// ---------------------------------------------------------------------------
// Swin WindowAttention, sm_103 base ISA.
//   QKV/out GEMMs: fp16 mma.sync m16n8k16 (BM=128 BN=128 BK=64); epilogue
//   staged through smem for STG.128. QKV writes hi plane (+lo for K only).
//   Attention: HMMA per (window,head): QK 2-pass (K hi/lo), softmax in
//   fragments, AV single pass (P hi x V hi).
// ---------------------------------------------------------------------------

#define N_WIN 4096
#define L_TOK 49
#define CH    256
#define NHEAD 8
#define DK    32
#define M_ROWS (N_WIN * L_TOK)   // 200704
#define BM_STRIDE 2404

__device__ __half g_xh[(size_t)M_ROWS * CH];
__device__ __half g_qh[(size_t)M_ROWS * 768];   // hi plane of qkv
__device__ __half g_ql[(size_t)M_ROWS * 768];   // lo plane (K section only)
__device__ __half g_ah[(size_t)M_ROWS * CH];    // attention output (fp16)
__device__ __half g_wqkv[256 * 768];
__device__ __half g_wo[256 * 256];
__device__ float  g_bm[512 * BM_STRIDE];

// ------------------------------ helpers ------------------------------------

__device__ __forceinline__ uint32_t smem_u32(const void* p) {
    uint32_t a;
    asm("{ .reg .u64 t; cvta.to.shared.u64 t, %1; cvt.u32.u64 %0, t; }"
        : "=r"(a) : "l"(p));
    return a;
}
__device__ __forceinline__ void cp16(uint32_t dst, const void* src) {
    asm volatile("cp.async.cg.shared.global [%0], [%1], 16;"
                 :: "r"(dst), "l"(src));
}
#define CP_COMMIT() asm volatile("cp.async.commit_group;" ::: "memory")
#define CP_WAIT1()  asm volatile("cp.async.wait_group 1;" ::: "memory")
#define CP_WAIT0()  asm volatile("cp.async.wait_group 0;" ::: "memory")

__device__ __forceinline__ void ldsm_x4(uint32_t addr, uint32_t* r) {
    asm volatile("ldmatrix.sync.aligned.m8n8.x4.shared.b16 {%0,%1,%2,%3}, [%4];"
                 : "=r"(r[0]), "=r"(r[1]), "=r"(r[2]), "=r"(r[3]) : "r"(addr));
}
__device__ __forceinline__ void ldsm_x4_t(uint32_t addr, uint32_t* r) {
    asm volatile("ldmatrix.sync.aligned.m8n8.x4.trans.shared.b16 {%0,%1,%2,%3}, [%4];"
                 : "=r"(r[0]), "=r"(r[1]), "=r"(r[2]), "=r"(r[3]) : "r"(addr));
}
__device__ __forceinline__ void mma16816(float* c, const uint32_t* a,
                                         const uint32_t* b) {
    asm volatile(
        "mma.sync.aligned.m16n8k16.row.col.f32.f16.f16.f32 "
        "{%0,%1,%2,%3}, {%4,%5,%6,%7}, {%8,%9}, {%0,%1,%2,%3};"
        : "+f"(c[0]), "+f"(c[1]), "+f"(c[2]), "+f"(c[3])
        : "r"(a[0]), "r"(a[1]), "r"(a[2]), "r"(a[3]), "r"(b[0]), "r"(b[1]));
}
__device__ __forceinline__ uint32_t pack_h2(float x, float y) {
    __half2 v = __halves2half2(__float2half_rn(x), __float2half_rn(y));
    return *(uint32_t*)&v;
}

// ------------------------------ prep kernels --------------------------------

__global__ void k_split_x(const float* __restrict__ x) {
    int i = blockIdx.x * blockDim.x + threadIdx.x;
    if (i >= (M_ROWS * CH) / 4) return;
    float4 v = ((const float4*)x)[i];
    ((__half2*)g_xh)[i * 2] =
        __halves2half2(__float2half_rn(v.x), __float2half_rn(v.y));
    ((__half2*)g_xh)[i * 2 + 1] =
        __halves2half2(__float2half_rn(v.z), __float2half_rn(v.w));
}

__global__ void k_split_w(const float* __restrict__ wq,
                          const float* __restrict__ wk,
                          const float* __restrict__ wv,
                          const float* __restrict__ wo) {
    int gid = blockIdx.x * blockDim.x + threadIdx.x;
    if (gid >= 65536) return;
    int sect = gid >> 14;
    int i    = gid & 16383;
    const float* src = (sect == 0) ? wq : (sect == 1) ? wk
                     : (sect == 2) ? wv : wo;
    float4 v = ((const float4*)src)[i];
    __half2 a = __halves2half2(__float2half_rn(v.x), __float2half_rn(v.y));
    __half2 b = __halves2half2(__float2half_rn(v.z), __float2half_rn(v.w));
    int k = (i * 4) >> 8;
    int n = (i * 4) & 255;
    if (sect < 3) {
        __half2* d = (__half2*)&g_wqkv[(size_t)k * 768 + sect * 256 + n];
        d[0] = a; d[1] = b;
    } else {
        __half2* d = (__half2*)&g_wo[(size_t)k * 256 + n];
        d[0] = a; d[1] = b;
    }
}

__global__ void k_bm(const float* __restrict__ mask,
                     const float* __restrict__ bias_table,
                     const int* __restrict__ rel_index) {
    const int bid = blockIdx.x;
    const int w   = bid >> 3;
    const int h   = bid & 7;
    float* dst = g_bm + (size_t)bid * BM_STRIDE;
    const float* mrow = mask + (size_t)w * (L_TOK * L_TOK);
    for (int i = threadIdx.x; i < L_TOK * L_TOK; i += blockDim.x)
        dst[i] = bias_table[rel_index[i] * NHEAD + h] + mrow[i];
}

// ------------------------------ GEMM ----------------------------------------

#define AROWH 72
#define BROWH 136
#define O_A 0
#define O_B 18432
#define S_BUF 35840
#define SMEM_BYTES (2 * S_BUF)
#define CS 136

__global__ __launch_bounds__(256, 2)
void k_hgemm(const __half* __restrict__ Ah, const __half* __restrict__ Wh,
             int ldW, float* __restrict__ Cf, int ldC, int mode)
{
    extern __shared__ char smem[];
    const uint32_t sb = smem_u32(smem);
    const int tid  = threadIdx.x;
    const int lane = tid & 31;
    const int wid  = tid >> 5;
    const int warp_m = wid & 3;
    const int warp_n = wid >> 2;
    const int rowBlock = blockIdx.y * 128;
    const int col0     = blockIdx.x * 128;

    float acc[2][8][4];
#pragma unroll
    for (int mt = 0; mt < 2; mt++)
#pragma unroll
        for (int nt = 0; nt < 8; nt++)
#pragma unroll
            for (int i = 0; i < 4; i++) acc[mt][nt][i] = 0.f;

    auto issue = [&](int c, int buf) {
        uint32_t s = sb + buf * S_BUF;
#pragma unroll
        for (int q4 = 0; q4 < 4; q4++) {
            int q   = tid + 256 * q4;
            int row = q >> 3;
            int seg = (q & 7) * 8;
            cp16(s + O_A + row * (AROWH * 2) + seg * 2,
                 Ah + (size_t)(rowBlock + row) * CH + c * 64 + seg);
        }
#pragma unroll
        for (int q4 = 0; q4 < 4; q4++) {
            int q   = tid + 256 * q4;
            int k   = q >> 4;
            int seg = (q & 15) * 8;
            cp16(s + O_B + k * (BROWH * 2) + seg * 2,
                 Wh + (size_t)(c * 64 + k) * ldW + col0 + seg);
        }
        CP_COMMIT();
    };

    const int arow_l = warp_m * 32 + (lane & 15);
    const int acol_l = (lane >> 4) * 8;
    const int brow_l = (lane & 7) + ((lane >> 3) & 1) * 8;
    const int bcol_l = warp_n * 64 + (lane >> 4) * 8;

    issue(0, 0);

#pragma unroll 1
    for (int c = 0; c < 4; c++) {
        if (c < 3) { issue(c + 1, (c + 1) & 1); CP_WAIT1(); }
        else       { CP_WAIT0(); }
        __syncthreads();

        const uint32_t s = sb + (c & 1) * S_BUF;
#pragma unroll
        for (int ks = 0; ks < 4; ks++) {
            uint32_t a[2][4], b[4][4];
            const uint32_t aoff = (acol_l + ks * 16) * 2;
#pragma unroll
            for (int mt = 0; mt < 2; mt++)
                ldsm_x4(s + O_A + (arow_l + mt * 16) * (AROWH * 2) + aoff,
                        a[mt]);
            const uint32_t brow = (brow_l + ks * 16) * (BROWH * 2);
#pragma unroll
            for (int np = 0; np < 4; np++)
                ldsm_x4_t(s + O_B + brow + (bcol_l + np * 16) * 2, b[np]);
#pragma unroll
            for (int mt = 0; mt < 2; mt++)
#pragma unroll
                for (int nt = 0; nt < 8; nt++)
                    mma16816(acc[mt][nt], a[mt], &b[nt >> 1][(nt & 1) * 2]);
        }
        __syncthreads();
    }

    // ---- epilogue via smem -> STG.128 ----
    float* cs = (float*)smem;
    const int g  = lane >> 2;
    const int tc = (lane & 3) * 2;
#pragma unroll
    for (int mt = 0; mt < 2; mt++) {
        const int r = warp_m * 32 + mt * 16 + g;
#pragma unroll
        for (int nt = 0; nt < 8; nt++) {
            const int cc = warp_n * 64 + nt * 8 + tc;
            *(float2*)&cs[r * CS + cc] =
                make_float2(acc[mt][nt][0], acc[mt][nt][1]);
            *(float2*)&cs[(r + 8) * CS + cc] =
                make_float2(acc[mt][nt][2], acc[mt][nt][3]);
        }
    }
    __syncthreads();

    const bool wlo = (col0 >= 256) && (col0 < 512);   // K section only
#pragma unroll
    for (int i = 0; i < 8; i++) {
        const int id  = tid + 256 * i;
        const int row = id >> 4;
        const int col = (id & 15) * 8;
        float4 v0 = *(float4*)&cs[row * CS + col];
        float4 v1 = *(float4*)&cs[row * CS + col + 4];
        if (mode == 0) {
            uint4 hi;
            hi.x = pack_h2(v0.x, v0.y); hi.y = pack_h2(v0.z, v0.w);
            hi.z = pack_h2(v1.x, v1.y); hi.w = pack_h2(v1.z, v1.w);
            size_t o = (size_t)(rowBlock + row) * 768 + col0 + col;
            *(uint4*)&g_qh[o] = hi;
            if (wlo) {
                __half2* hp = (__half2*)&hi;
                uint4 lo;
                lo.x = pack_h2(v0.x - __low2float(hp[0]),
                               v0.y - __high2float(hp[0]));
                lo.y = pack_h2(v0.z - __low2float(hp[1]),
                               v0.w - __high2float(hp[1]));
                lo.z = pack_h2(v1.x - __low2float(hp[2]),
                               v1.y - __high2float(hp[2]));
                lo.w = pack_h2(v1.z - __low2float(hp[3]),
                               v1.w - __high2float(hp[3]));
                *(uint4*)&g_ql[o] = lo;
            }
        } else {
            size_t o = (size_t)(rowBlock + row) * ldC + col0 + col;
            *(float4*)&Cf[o]     = v0;
            *(float4*)&Cf[o + 4] = v1;
        }
    }
}

// ------------------------------ attention (HMMA) ----------------------------
// QK 2-pass (K hi/lo), AV single pass (P hi x V hi).

#define KSTR 40

__global__ __launch_bounds__(128)
void attn_kernel()
{
    __shared__ __align__(16) __half sQ [64 * KSTR];
    __shared__ __align__(16) __half sKh[64 * KSTR];
    __shared__ __align__(16) __half sKl[64 * KSTR];
    __shared__ __align__(16) __half sVh[64 * KSTR];
    __shared__ __align__(16) float  ssb[BM_STRIDE];

    const int bid = blockIdx.x;
    const int h   = bid & 7;
    const int n   = bid >> 3;
    const int tid = threadIdx.x;

    // zero V padding rows 49..63
    for (int idx = tid; idx < 60; idx += 128) {
        int r  = 49 + (idx >> 2);
        int q4 = idx & 3;
        *(int4*)(sVh + r * KSTR + q4 * 8) = make_int4(0, 0, 0, 0);
    }
    // load Q(hi), K(hi,lo), V(hi): 4 planes x 49 rows x 4 int4
    {
        const size_t rb = (size_t)n * L_TOK * 768 + h * DK;
        for (int idx = tid; idx < 4 * 196; idx += 128) {
            int p   = idx / 196;
            int rem = idx - p * 196;
            int r   = rem >> 2;
            int q4  = rem & 3;
            const __half* src;
            __half* dst;
            switch (p) {
                case 0: src = g_qh + rb;       dst = sQ;  break;
                case 1: src = g_qh + rb + 256; dst = sKh; break;
                case 2: src = g_ql + rb + 256; dst = sKl; break;
                default: src = g_qh + rb + 512; dst = sVh; break;
            }
            *(int4*)(dst + r * KSTR + q4 * 8) =
                *(const int4*)(src + (size_t)r * 768 + q4 * 8);
        }
    }
    {
        const float* bm = g_bm + (size_t)(((n & 63) << 3) | h) * BM_STRIDE;
        for (int idx = tid; idx < BM_STRIDE / 4; idx += 128)
            ((int4*)ssb)[idx] = ((const int4*)bm)[idx];
    }
    __syncthreads();

    const int warp = tid >> 5;
    const int lane = tid & 31;
    const int g    = lane >> 2;
    const int t    = lane & 3;

    const uint32_t bq  = smem_u32(sQ);
    const uint32_t bkh = smem_u32(sKh);
    const uint32_t bkl = smem_u32(sKl);
    const int aRow = warp * 16 + (lane & 15);
    const int aCol = (lane >> 4) * 8;

    uint32_t qa[2][4];
    ldsm_x4(bq + (aRow * KSTR + aCol) * 2, qa[0]);
    ldsm_x4(bq + (aRow * KSTR + aCol + 16) * 2, qa[1]);

    float c[8][4];
#pragma unroll
    for (int nt = 0; nt < 8; nt++)
#pragma unroll
        for (int i = 0; i < 4; i++) c[nt][i] = 0.f;

#pragma unroll
    for (int pass = 0; pass < 2; pass++) {
        const uint32_t base = pass ? bkl : bkh;
#pragma unroll
        for (int kt = 0; kt < 2; kt++) {
#pragma unroll
            for (int jp = 0; jp < 4; jp++) {
                uint32_t kb[4];
                ldsm_x4(base + ((jp * 16 + (lane & 15)) * KSTR +
                                (lane >> 4) * 8 + kt * 16) * 2, kb);
                uint32_t b0[2] = {kb[0], kb[2]};
                uint32_t b1[2] = {kb[1], kb[3]};
                mma16816(c[jp * 2],     qa[kt], b0);
                mma16816(c[jp * 2 + 1], qa[kt], b1);
            }
        }
    }

    const int r0 = warp * 16 + g;
    const int r1 = r0 + 8;
    const int r0c = (r0 < L_TOK ? r0 : L_TOK - 1) * L_TOK;
    const int r1c = (r1 < L_TOK ? r1 : L_TOK - 1) * L_TOK;
#pragma unroll
    for (int nt = 0; nt < 8; nt++) {
        const int j0 = nt * 8 + t * 2;
        if (j0 < L_TOK) {
            c[nt][0] += ssb[r0c + j0];
            c[nt][2] += ssb[r1c + j0];
        } else { c[nt][0] = -3.0e38f; c[nt][2] = -3.0e38f; }
        if (j0 + 1 < L_TOK) {
            c[nt][1] += ssb[r0c + j0 + 1];
            c[nt][3] += ssb[r1c + j0 + 1];
        } else { c[nt][1] = -3.0e38f; c[nt][3] = -3.0e38f; }
    }

    float mx0 = -3.0e38f, mx1 = -3.0e38f;
#pragma unroll
    for (int nt = 0; nt < 8; nt++) {
        mx0 = fmaxf(mx0, fmaxf(c[nt][0], c[nt][1]));
        mx1 = fmaxf(mx1, fmaxf(c[nt][2], c[nt][3]));
    }
    mx0 = fmaxf(mx0, __shfl_xor_sync(0xffffffffu, mx0, 1));
    mx0 = fmaxf(mx0, __shfl_xor_sync(0xffffffffu, mx0, 2));
    mx1 = fmaxf(mx1, __shfl_xor_sync(0xffffffffu, mx1, 1));
    mx1 = fmaxf(mx1, __shfl_xor_sync(0xffffffffu, mx1, 2));

    float s0 = 0.f, s1 = 0.f;
#pragma unroll
    for (int nt = 0; nt < 8; nt++) {
        c[nt][0] = __expf(c[nt][0] - mx0); s0 += c[nt][0];
        c[nt][1] = __expf(c[nt][1] - mx0); s0 += c[nt][1];
        c[nt][2] = __expf(c[nt][2] - mx1); s1 += c[nt][2];
        c[nt][3] = __expf(c[nt][3] - mx1); s1 += c[nt][3];
    }
    s0 += __shfl_xor_sync(0xffffffffu, s0, 1);
    s0 += __shfl_xor_sync(0xffffffffu, s0, 2);
    s1 += __shfl_xor_sync(0xffffffffu, s1, 1);
    s1 += __shfl_xor_sync(0xffffffffu, s1, 2);
    const float rs0 = 1.f / s0;
    const float rs1 = 1.f / s1;

    // ---- AV: single pass Ph x Vh ----
    const uint32_t bvh = smem_u32(sVh);
    const int vRow = (lane & 7) + ((lane >> 3) & 1) * 8;
    const int vCol = (lane >> 4) * 8;

    float o[4][4];
#pragma unroll
    for (int nt = 0; nt < 4; nt++)
#pragma unroll
        for (int i = 0; i < 4; i++) o[nt][i] = 0.f;

#pragma unroll
    for (int kt = 0; kt < 4; kt++) {
        uint32_t ph[4];
#pragma unroll
        for (int q = 0; q < 2; q++) {
            const float* cc = c[2 * kt + q];
            ph[q * 2]     = pack_h2(cc[0], cc[1]);
            ph[q * 2 + 1] = pack_h2(cc[2], cc[3]);
        }
        uint32_t vh[2][4];
        const uint32_t roff = (kt * 16 + vRow) * KSTR;
        ldsm_x4_t(bvh + (roff + vCol) * 2,      vh[0]);
        ldsm_x4_t(bvh + (roff + vCol + 16) * 2, vh[1]);
#pragma unroll
        for (int nt = 0; nt < 4; nt++)
            mma16816(o[nt], ph, &vh[nt >> 1][(nt & 1) * 2]);
    }

    if (r0 < L_TOK) {
        __half* orow = g_ah + (size_t)(n * L_TOK + r0) * CH + h * DK;
#pragma unroll
        for (int nt = 0; nt < 4; nt++)
            *(__half2*)&orow[nt * 8 + t * 2] =
                __halves2half2(__float2half_rn(o[nt][0] * rs0),
                               __float2half_rn(o[nt][1] * rs0));
    }
    if (r1 < L_TOK) {
        __half* orow = g_ah + (size_t)(n * L_TOK + r1) * CH + h * DK;
#pragma unroll
        for (int nt = 0; nt < 4; nt++)
            *(__half2*)&orow[nt * 8 + t * 2] =
                __halves2half2(__float2half_rn(o[nt][2] * rs1),
                               __float2half_rn(o[nt][3] * rs1));
    }
}

// ------------------------------- launch --------------------------------------

extern "C" void kernel_launch(void* const* d_in, const int* in_sizes, int n_in,
                              void* d_out, int out_size)
{
    (void)in_sizes; (void)n_in; (void)out_size;
    const float* x    = (const float*)d_in[0];
    const float* mask = (const float*)d_in[1];
    const float* wq   = (const float*)d_in[2];
    const float* wk   = (const float*)d_in[3];
    const float* wv   = (const float*)d_in[4];
    const float* wo   = (const float*)d_in[5];
    const float* bias = (const float*)d_in[6];
    const int*   rel  = (const int*)d_in[7];
    float* out = (float*)d_out;

    static __half *xh = nullptr, *ah = nullptr, *wqkv = nullptr, *woh = nullptr;
    if (!xh) {
        cudaGetSymbolAddress((void**)&xh,   g_xh);
        cudaGetSymbolAddress((void**)&ah,   g_ah);
        cudaGetSymbolAddress((void**)&wqkv, g_wqkv);
        cudaGetSymbolAddress((void**)&woh,  g_wo);
        cudaFuncSetAttribute(k_hgemm,
                             cudaFuncAttributeMaxDynamicSharedMemorySize,
                             SMEM_BYTES);
    }

    k_split_x<<<(M_ROWS * CH / 4 + 255) / 256, 256>>>(x);
    k_split_w<<<256, 256>>>(wq, wk, wv, wo);
    k_bm<<<512, 256>>>(mask, bias, rel);
    k_hgemm<<<dim3(6, M_ROWS / 128), 256, SMEM_BYTES>>>(xh, wqkv, 768,
                                                        nullptr, 768, 0);
    attn_kernel<<<N_WIN * NHEAD, 128>>>();
    k_hgemm<<<dim3(2, M_ROWS / 128), 256, SMEM_BYTES>>>(ah, woh, 256,
                                                        out, 256, 1);
}

// round 10
// speedup vs baseline: 6.1067x; 1.1199x over previous
#include <cuda_runtime.h>
#include <cuda_fp16.h>
#include <cstdint>

// ---------------------------------------------------------------------------
// Swin WindowAttention, sm_103 base ISA.
//   GEMMs: fp16 mma.sync m16n8k16, BM=128 BN=128 BK=64, 4 warps each 64x64
//   (high arithmetic intensity vs smem crossbar). Epilogue staged via smem.
//   QKV writes hi plane (+lo for K section).
//   Attention: HMMA per (window,head): QK 2-pass, AV 1-pass; bias+mask
//   loaded directly from L2 (no smem staging).
// ---------------------------------------------------------------------------

#define N_WIN 4096
#define L_TOK 49
#define CH    256
#define NHEAD 8
#define DK    32
#define M_ROWS (N_WIN * L_TOK)   // 200704
#define BMROW 52                 // bias+mask row stride (floats, 8B aligned)
#define BMWIN 2560               // per (window,head) stride

__device__ __half g_xh[(size_t)M_ROWS * CH];
__device__ __half g_qh[(size_t)M_ROWS * 768];
__device__ __half g_ql[(size_t)M_ROWS * 768];
__device__ __half g_ah[(size_t)M_ROWS * CH];
__device__ __half g_wqkv[256 * 768];
__device__ __half g_wo[256 * 256];
__device__ float  g_bm[512 * BMWIN];

// ------------------------------ helpers ------------------------------------

__device__ __forceinline__ uint32_t smem_u32(const void* p) {
    uint32_t a;
    asm("{ .reg .u64 t; cvta.to.shared.u64 t, %1; cvt.u32.u64 %0, t; }"
        : "=r"(a) : "l"(p));
    return a;
}
__device__ __forceinline__ void cp16(uint32_t dst, const void* src) {
    asm volatile("cp.async.cg.shared.global [%0], [%1], 16;"
                 :: "r"(dst), "l"(src));
}
#define CP_COMMIT() asm volatile("cp.async.commit_group;" ::: "memory")
#define CP_WAIT1()  asm volatile("cp.async.wait_group 1;" ::: "memory")
#define CP_WAIT0()  asm volatile("cp.async.wait_group 0;" ::: "memory")

__device__ __forceinline__ void ldsm_x4(uint32_t addr, uint32_t* r) {
    asm volatile("ldmatrix.sync.aligned.m8n8.x4.shared.b16 {%0,%1,%2,%3}, [%4];"
                 : "=r"(r[0]), "=r"(r[1]), "=r"(r[2]), "=r"(r[3]) : "r"(addr));
}
__device__ __forceinline__ void ldsm_x4_t(uint32_t addr, uint32_t* r) {
    asm volatile("ldmatrix.sync.aligned.m8n8.x4.trans.shared.b16 {%0,%1,%2,%3}, [%4];"
                 : "=r"(r[0]), "=r"(r[1]), "=r"(r[2]), "=r"(r[3]) : "r"(addr));
}
__device__ __forceinline__ void mma16816(float* c, const uint32_t* a,
                                         const uint32_t* b) {
    asm volatile(
        "mma.sync.aligned.m16n8k16.row.col.f32.f16.f16.f32 "
        "{%0,%1,%2,%3}, {%4,%5,%6,%7}, {%8,%9}, {%0,%1,%2,%3};"
        : "+f"(c[0]), "+f"(c[1]), "+f"(c[2]), "+f"(c[3])
        : "r"(a[0]), "r"(a[1]), "r"(a[2]), "r"(a[3]), "r"(b[0]), "r"(b[1]));
}
__device__ __forceinline__ uint32_t pack_h2(float x, float y) {
    __half2 v = __halves2half2(__float2half_rn(x), __float2half_rn(y));
    return *(uint32_t*)&v;
}

// ------------------------------ prep kernels --------------------------------

__global__ void k_split_x(const float* __restrict__ x) {
    int i = blockIdx.x * blockDim.x + threadIdx.x;
    if (i >= (M_ROWS * CH) / 4) return;
    float4 v = ((const float4*)x)[i];
    ((__half2*)g_xh)[i * 2] =
        __halves2half2(__float2half_rn(v.x), __float2half_rn(v.y));
    ((__half2*)g_xh)[i * 2 + 1] =
        __halves2half2(__float2half_rn(v.z), __float2half_rn(v.w));
}

__global__ void k_split_w(const float* __restrict__ wq,
                          const float* __restrict__ wk,
                          const float* __restrict__ wv,
                          const float* __restrict__ wo) {
    int gid = blockIdx.x * blockDim.x + threadIdx.x;
    if (gid >= 65536) return;
    int sect = gid >> 14;
    int i    = gid & 16383;
    const float* src = (sect == 0) ? wq : (sect == 1) ? wk
                     : (sect == 2) ? wv : wo;
    float4 v = ((const float4*)src)[i];
    __half2 a = __halves2half2(__float2half_rn(v.x), __float2half_rn(v.y));
    __half2 b = __halves2half2(__float2half_rn(v.z), __float2half_rn(v.w));
    int k = (i * 4) >> 8;
    int n = (i * 4) & 255;
    if (sect < 3) {
        __half2* d = (__half2*)&g_wqkv[(size_t)k * 768 + sect * 256 + n];
        d[0] = a; d[1] = b;
    } else {
        __half2* d = (__half2*)&g_wo[(size_t)k * 256 + n];
        d[0] = a; d[1] = b;
    }
}

__global__ void k_bm(const float* __restrict__ mask,
                     const float* __restrict__ bias_table,
                     const int* __restrict__ rel_index) {
    const int bid = blockIdx.x;
    const int w   = bid >> 3;
    const int h   = bid & 7;
    float* dst = g_bm + (size_t)bid * BMWIN;
    const float* mrow = mask + (size_t)w * (L_TOK * L_TOK);
    for (int i = threadIdx.x; i < L_TOK * L_TOK; i += blockDim.x)
        dst[(i / L_TOK) * BMROW + (i % L_TOK)] =
            bias_table[rel_index[i] * NHEAD + h] + mrow[i];
}

// ------------------------------ GEMM ----------------------------------------
// BM=128 BN=128 BK=64, 4 warps (2m x 2n), warp tile 64x64.

#define AROWH 72
#define BROWH 136
#define O_A 0
#define O_B 18432
#define S_BUF 35840
#define SMEM_BYTES (2 * S_BUF)
#define CS 136

__global__ __launch_bounds__(128, 2)
void k_hgemm(const __half* __restrict__ Ah, const __half* __restrict__ Wh,
             int ldW, float* __restrict__ Cf, int ldC, int mode)
{
    extern __shared__ char smem[];
    const uint32_t sb = smem_u32(smem);
    const int tid  = threadIdx.x;
    const int lane = tid & 31;
    const int wid  = tid >> 5;
    const int warp_m = wid & 1;        // 64 rows each
    const int warp_n = wid >> 1;       // 64 cols each
    const int rowBlock = blockIdx.y * 128;
    const int col0     = blockIdx.x * 128;

    float acc[4][8][4];
#pragma unroll
    for (int mt = 0; mt < 4; mt++)
#pragma unroll
        for (int nt = 0; nt < 8; nt++)
#pragma unroll
            for (int i = 0; i < 4; i++) acc[mt][nt][i] = 0.f;

    auto issue = [&](int c, int buf) {
        uint32_t s = sb + buf * S_BUF;
#pragma unroll
        for (int q8 = 0; q8 < 8; q8++) {
            int q   = tid + 128 * q8;          // 0..1023
            int row = q >> 3;
            int seg = (q & 7) * 8;
            cp16(s + O_A + row * (AROWH * 2) + seg * 2,
                 Ah + (size_t)(rowBlock + row) * CH + c * 64 + seg);
        }
#pragma unroll
        for (int q8 = 0; q8 < 8; q8++) {
            int q   = tid + 128 * q8;
            int k   = q >> 4;
            int seg = (q & 15) * 8;
            cp16(s + O_B + k * (BROWH * 2) + seg * 2,
                 Wh + (size_t)(c * 64 + k) * ldW + col0 + seg);
        }
        CP_COMMIT();
    };

    const int arow_l = warp_m * 64 + (lane & 15);
    const int acol_l = (lane >> 4) * 8;
    const int brow_l = (lane & 7) + ((lane >> 3) & 1) * 8;
    const int bcol_l = warp_n * 64 + (lane >> 4) * 8;

    issue(0, 0);

#pragma unroll 1
    for (int c = 0; c < 4; c++) {
        if (c < 3) { issue(c + 1, (c + 1) & 1); CP_WAIT1(); }
        else       { CP_WAIT0(); }
        __syncthreads();

        const uint32_t s = sb + (c & 1) * S_BUF;
#pragma unroll
        for (int ks = 0; ks < 4; ks++) {
            uint32_t a[4][4], b[4][4];
            const uint32_t aoff = (acol_l + ks * 16) * 2;
#pragma unroll
            for (int mt = 0; mt < 4; mt++)
                ldsm_x4(s + O_A + (arow_l + mt * 16) * (AROWH * 2) + aoff,
                        a[mt]);
            const uint32_t brow = (brow_l + ks * 16) * (BROWH * 2);
#pragma unroll
            for (int np = 0; np < 4; np++)
                ldsm_x4_t(s + O_B + brow + (bcol_l + np * 16) * 2, b[np]);
#pragma unroll
            for (int mt = 0; mt < 4; mt++)
#pragma unroll
                for (int nt = 0; nt < 8; nt++)
                    mma16816(acc[mt][nt], a[mt], &b[nt >> 1][(nt & 1) * 2]);
        }
        __syncthreads();
    }

    // ---- epilogue via smem -> STG.128 ----
    float* cs = (float*)smem;
    const int g  = lane >> 2;
    const int tc = (lane & 3) * 2;
#pragma unroll
    for (int mt = 0; mt < 4; mt++) {
        const int r = warp_m * 64 + mt * 16 + g;
#pragma unroll
        for (int nt = 0; nt < 8; nt++) {
            const int cc = warp_n * 64 + nt * 8 + tc;
            *(float2*)&cs[r * CS + cc] =
                make_float2(acc[mt][nt][0], acc[mt][nt][1]);
            *(float2*)&cs[(r + 8) * CS + cc] =
                make_float2(acc[mt][nt][2], acc[mt][nt][3]);
        }
    }
    __syncthreads();

    const bool wlo = (col0 >= 256) && (col0 < 512);   // K section only
#pragma unroll
    for (int i = 0; i < 16; i++) {
        const int id  = tid + 128 * i;
        const int row = id >> 4;
        const int col = (id & 15) * 8;
        float4 v0 = *(float4*)&cs[row * CS + col];
        float4 v1 = *(float4*)&cs[row * CS + col + 4];
        if (mode == 0) {
            uint4 hi;
            hi.x = pack_h2(v0.x, v0.y); hi.y = pack_h2(v0.z, v0.w);
            hi.z = pack_h2(v1.x, v1.y); hi.w = pack_h2(v1.z, v1.w);
            size_t o = (size_t)(rowBlock + row) * 768 + col0 + col;
            *(uint4*)&g_qh[o] = hi;
            if (wlo) {
                __half2* hp = (__half2*)&hi;
                uint4 lo;
                lo.x = pack_h2(v0.x - __low2float(hp[0]),
                               v0.y - __high2float(hp[0]));
                lo.y = pack_h2(v0.z - __low2float(hp[1]),
                               v0.w - __high2float(hp[1]));
                lo.z = pack_h2(v1.x - __low2float(hp[2]),
                               v1.y - __high2float(hp[2]));
                lo.w = pack_h2(v1.z - __low2float(hp[3]),
                               v1.w - __high2float(hp[3]));
                *(uint4*)&g_ql[o] = lo;
            }
        } else {
            size_t o = (size_t)(rowBlock + row) * ldC + col0 + col;
            *(float4*)&Cf[o]     = v0;
            *(float4*)&Cf[o + 4] = v1;
        }
    }
}

// ------------------------------ attention (HMMA) ----------------------------

#define KSTR 40

__global__ __launch_bounds__(128)
void attn_kernel()
{
    __shared__ __align__(16) __half sQ [64 * KSTR];
    __shared__ __align__(16) __half sKh[64 * KSTR];
    __shared__ __align__(16) __half sKl[64 * KSTR];
    __shared__ __align__(16) __half sVh[64 * KSTR];

    const int bid = blockIdx.x;
    const int h   = bid & 7;
    const int n   = bid >> 3;
    const int tid = threadIdx.x;

    for (int idx = tid; idx < 60; idx += 128) {
        int r  = 49 + (idx >> 2);
        int q4 = idx & 3;
        *(int4*)(sVh + r * KSTR + q4 * 8) = make_int4(0, 0, 0, 0);
    }
    {
        const size_t rb = (size_t)n * L_TOK * 768 + h * DK;
        for (int idx = tid; idx < 4 * 196; idx += 128) {
            int p   = idx / 196;
            int rem = idx - p * 196;
            int r   = rem >> 2;
            int q4  = rem & 3;
            const __half* src;
            __half* dst;
            switch (p) {
                case 0: src = g_qh + rb;       dst = sQ;  break;
                case 1: src = g_qh + rb + 256; dst = sKh; break;
                case 2: src = g_ql + rb + 256; dst = sKl; break;
                default: src = g_qh + rb + 512; dst = sVh; break;
            }
            *(int4*)(dst + r * KSTR + q4 * 8) =
                *(const int4*)(src + (size_t)r * 768 + q4 * 8);
        }
    }
    __syncthreads();

    const int warp = tid >> 5;
    const int lane = tid & 31;
    const int g    = lane >> 2;
    const int t    = lane & 3;

    const uint32_t bq  = smem_u32(sQ);
    const uint32_t bkh = smem_u32(sKh);
    const uint32_t bkl = smem_u32(sKl);
    const int aRow = warp * 16 + (lane & 15);
    const int aCol = (lane >> 4) * 8;

    uint32_t qa[2][4];
    ldsm_x4(bq + (aRow * KSTR + aCol) * 2, qa[0]);
    ldsm_x4(bq + (aRow * KSTR + aCol + 16) * 2, qa[1]);

    float c[8][4];
#pragma unroll
    for (int nt = 0; nt < 8; nt++)
#pragma unroll
        for (int i = 0; i < 4; i++) c[nt][i] = 0.f;

#pragma unroll
    for (int pass = 0; pass < 2; pass++) {
        const uint32_t base = pass ? bkl : bkh;
#pragma unroll
        for (int kt = 0; kt < 2; kt++) {
#pragma unroll
            for (int jp = 0; jp < 4; jp++) {
                uint32_t kb[4];
                ldsm_x4(base + ((jp * 16 + (lane & 15)) * KSTR +
                                (lane >> 4) * 8 + kt * 16) * 2, kb);
                uint32_t b0[2] = {kb[0], kb[2]};
                uint32_t b1[2] = {kb[1], kb[3]};
                mma16816(c[jp * 2],     qa[kt], b0);
                mma16816(c[jp * 2 + 1], qa[kt], b1);
            }
        }
    }

    // ---- bias+mask direct from L2, softmax ----
    const int r0 = warp * 16 + g;
    const int r1 = r0 + 8;
    const float* bm = g_bm + (size_t)(((n & 63) << 3) | h) * BMWIN;
    const int r0e = (r0 < L_TOK ? r0 : L_TOK - 1) * BMROW;
    const int r1e = (r1 < L_TOK ? r1 : L_TOK - 1) * BMROW;
#pragma unroll
    for (int nt = 0; nt < 8; nt++) {
        const int j0 = nt * 8 + t * 2;
        if (j0 < L_TOK) {
            float2 b0 = __ldg((const float2*)&bm[r0e + j0]);
            float2 b1 = __ldg((const float2*)&bm[r1e + j0]);
            c[nt][0] += b0.x;
            c[nt][2] += b1.x;
            if (j0 + 1 < L_TOK) { c[nt][1] += b0.y; c[nt][3] += b1.y; }
            else { c[nt][1] = -3.0e38f; c[nt][3] = -3.0e38f; }
        } else {
            c[nt][0] = c[nt][1] = c[nt][2] = c[nt][3] = -3.0e38f;
        }
    }

    float mx0 = -3.0e38f, mx1 = -3.0e38f;
#pragma unroll
    for (int nt = 0; nt < 8; nt++) {
        mx0 = fmaxf(mx0, fmaxf(c[nt][0], c[nt][1]));
        mx1 = fmaxf(mx1, fmaxf(c[nt][2], c[nt][3]));
    }
    mx0 = fmaxf(mx0, __shfl_xor_sync(0xffffffffu, mx0, 1));
    mx0 = fmaxf(mx0, __shfl_xor_sync(0xffffffffu, mx0, 2));
    mx1 = fmaxf(mx1, __shfl_xor_sync(0xffffffffu, mx1, 1));
    mx1 = fmaxf(mx1, __shfl_xor_sync(0xffffffffu, mx1, 2));

    float s0 = 0.f, s1 = 0.f;
#pragma unroll
    for (int nt = 0; nt < 8; nt++) {
        c[nt][0] = __expf(c[nt][0] - mx0); s0 += c[nt][0];
        c[nt][1] = __expf(c[nt][1] - mx0); s0 += c[nt][1];
        c[nt][2] = __expf(c[nt][2] - mx1); s1 += c[nt][2];
        c[nt][3] = __expf(c[nt][3] - mx1); s1 += c[nt][3];
    }
    s0 += __shfl_xor_sync(0xffffffffu, s0, 1);
    s0 += __shfl_xor_sync(0xffffffffu, s0, 2);
    s1 += __shfl_xor_sync(0xffffffffu, s1, 1);
    s1 += __shfl_xor_sync(0xffffffffu, s1, 2);
    const float rs0 = 1.f / s0;
    const float rs1 = 1.f / s1;

    // ---- AV: single pass ----
    const uint32_t bvh = smem_u32(sVh);
    const int vRow = (lane & 7) + ((lane >> 3) & 1) * 8;
    const int vCol = (lane >> 4) * 8;

    float o[4][4];
#pragma unroll
    for (int nt = 0; nt < 4; nt++)
#pragma unroll
        for (int i = 0; i < 4; i++) o[nt][i] = 0.f;

#pragma unroll
    for (int kt = 0; kt < 4; kt++) {
        uint32_t ph[4];
#pragma unroll
        for (int q = 0; q < 2; q++) {
            const float* cc = c[2 * kt + q];
            ph[q * 2]     = pack_h2(cc[0], cc[1]);
            ph[q * 2 + 1] = pack_h2(cc[2], cc[3]);
        }
        uint32_t vh[2][4];
        const uint32_t roff = (kt * 16 + vRow) * KSTR;
        ldsm_x4_t(bvh + (roff + vCol) * 2,      vh[0]);
        ldsm_x4_t(bvh + (roff + vCol + 16) * 2, vh[1]);
#pragma unroll
        for (int nt = 0; nt < 4; nt++)
            mma16816(o[nt], ph, &vh[nt >> 1][(nt & 1) * 2]);
    }

    if (r0 < L_TOK) {
        __half* orow = g_ah + (size_t)(n * L_TOK + r0) * CH + h * DK;
#pragma unroll
        for (int nt = 0; nt < 4; nt++)
            *(__half2*)&orow[nt * 8 + t * 2] =
                __halves2half2(__float2half_rn(o[nt][0] * rs0),
                               __float2half_rn(o[nt][1] * rs0));
    }
    if (r1 < L_TOK) {
        __half* orow = g_ah + (size_t)(n * L_TOK + r1) * CH + h * DK;
#pragma unroll
        for (int nt = 0; nt < 4; nt++)
            *(__half2*)&orow[nt * 8 + t * 2] =
                __halves2half2(__float2half_rn(o[nt][2] * rs1),
                               __float2half_rn(o[nt][3] * rs1));
    }
}

// ------------------------------- launch --------------------------------------

extern "C" void kernel_launch(void* const* d_in, const int* in_sizes, int n_in,
                              void* d_out, int out_size)
{
    (void)in_sizes; (void)n_in; (void)out_size;
    const float* x    = (const float*)d_in[0];
    const float* mask = (const float*)d_in[1];
    const float* wq   = (const float*)d_in[2];
    const float* wk   = (const float*)d_in[3];
    const float* wv   = (const float*)d_in[4];
    const float* wo   = (const float*)d_in[5];
    const float* bias = (const float*)d_in[6];
    const int*   rel  = (const int*)d_in[7];
    float* out = (float*)d_out;

    static __half *xh = nullptr, *ah = nullptr, *wqkv = nullptr, *woh = nullptr;
    if (!xh) {
        cudaGetSymbolAddress((void**)&xh,   g_xh);
        cudaGetSymbolAddress((void**)&ah,   g_ah);
        cudaGetSymbolAddress((void**)&wqkv, g_wqkv);
        cudaGetSymbolAddress((void**)&woh,  g_wo);
        cudaFuncSetAttribute(k_hgemm,
                             cudaFuncAttributeMaxDynamicSharedMemorySize,
                             SMEM_BYTES);
    }

    k_split_x<<<(M_ROWS * CH / 4 + 255) / 256, 256>>>(x);
    k_split_w<<<256, 256>>>(wq, wk, wv, wo);
    k_bm<<<512, 256>>>(mask, bias, rel);
    k_hgemm<<<dim3(6, M_ROWS / 128), 128, SMEM_BYTES>>>(xh, wqkv, 768,
                                                        nullptr, 768, 0);
    attn_kernel<<<N_WIN * NHEAD, 128>>>();
    k_hgemm<<<dim3(2, M_ROWS / 128), 128, SMEM_BYTES>>>(ah, woh, 256,
                                                        out, 256, 1);
}